// round 1
// baseline (speedup 1.0000x reference)
#include <cuda_runtime.h>
#include <math.h>

#define Bdim 8
#define Ldim 2048
#define Cdim 512
#define Gdim 8
#define CG   64
#define Mdim (Bdim*Ldim)          // 16384
#define EPSV 1e-3f
#define SCALE 0.04419417382415922f  // 512^-0.5

// ---- scratch (device globals: allocation-free rule) ----
__device__ float g_h[Mdim*Cdim];
__device__ float g_q[Mdim*Cdim];
__device__ float g_k[Mdim*Cdim];
__device__ float g_v[Mdim*Cdim];
__device__ float g_o[Mdim*Cdim];
__device__ float g_s[(size_t)Bdim*Ldim*Ldim];   // 134 MB attention logits
__device__ float g_mean[Bdim*Gdim];
__device__ float g_rstd[Bdim*Gdim];

// ============================================================
// GroupNorm statistics: one block per (batch, group)
// ============================================================
__global__ void gn_stats(const float* __restrict__ x) {
    int bg = blockIdx.x;               // 0..63
    int b = bg >> 3, g = bg & 7;
    const float* base = x + (size_t)b * Ldim * Cdim + g * CG;
    float s = 0.f, ss = 0.f;
    for (int i = threadIdx.x; i < Ldim * CG; i += 256) {
        float v = base[(size_t)(i >> 6) * Cdim + (i & 63)];
        s += v; ss += v * v;
    }
    __shared__ float sh1[256], sh2[256];
    sh1[threadIdx.x] = s; sh2[threadIdx.x] = ss;
    __syncthreads();
    for (int o = 128; o > 0; o >>= 1) {
        if (threadIdx.x < o) {
            sh1[threadIdx.x] += sh1[threadIdx.x + o];
            sh2[threadIdx.x] += sh2[threadIdx.x + o];
        }
        __syncthreads();
    }
    if (threadIdx.x == 0) {
        const float inv = 1.f / (float)(Ldim * CG);
        float m = sh1[0] * inv;
        float var = sh2[0] * inv - m * m;
        g_mean[bg] = m;
        g_rstd[bg] = rsqrtf(var + EPSV);
    }
}

// ============================================================
// GroupNorm apply: h = (x - mean) * rstd * gamma + beta
// ============================================================
__global__ void gn_apply(const float4* __restrict__ x,
                         const float4* __restrict__ gamma,
                         const float4* __restrict__ beta) {
    int i = blockIdx.x * 256 + threadIdx.x;      // float4 index, exact grid
    int e = i * 4;
    int ch = e & (Cdim - 1);
    int row = e >> 9;
    int b = row >> 11;
    int g = ch >> 6;
    float m = g_mean[b * 8 + g], r = g_rstd[b * 8 + g];
    float4 xv = x[i];
    float4 ga = gamma[ch >> 2];
    float4 be = beta[ch >> 2];
    float4 hv;
    hv.x = (xv.x - m) * r * ga.x + be.x;
    hv.y = (xv.y - m) * r * ga.y + be.y;
    hv.z = (xv.z - m) * r * ga.z + be.z;
    hv.w = (xv.w - m) * r * ga.w + be.w;
    ((float4*)g_h)[i] = hv;
}

// ============================================================
// NN GEMM: C[M,N] = A[M,K] @ B[K,N] (+bias) (+res)
// 64x64 tile, BK=16, 256 threads, 4x4 microtile. Batched via z.
// All dims assumed multiples of tile sizes (true here).
// ============================================================
__global__ void __launch_bounds__(256)
gemm_nn(const float* __restrict__ A, const float* __restrict__ Bm,
        const float* __restrict__ bias, const float* __restrict__ res,
        float* __restrict__ C, int Nn, int Kn,
        long sA, long sB, long sC, long sR) {
    __shared__ float As[16][68];
    __shared__ float Bs[16][64];
    int z = blockIdx.z;
    A  += (size_t)z * sA;
    Bm += (size_t)z * sB;
    C  += (size_t)z * sC;
    const float* R = res ? res + (size_t)z * sR : nullptr;

    int bm = blockIdx.y * 64, bn = blockIdx.x * 64;
    int tid = threadIdx.x;
    int tx = tid & 15, ty = tid >> 4;
    int arow = tid >> 2,  ac4 = (tid & 3) * 4;    // A loader
    int brow = tid >> 4,  bc4 = (tid & 15) * 4;   // B loader

    const float* Aptr = A  + (size_t)(bm + arow) * Kn + ac4;
    const float* Bptr = Bm + (size_t)brow * Nn + bn + bc4;

    float acc[4][4] = {};

    for (int k0 = 0; k0 < Kn; k0 += 16) {
        float4 av = *(const float4*)Aptr; Aptr += 16;
        float4 bv = *(const float4*)Bptr; Bptr += (size_t)16 * Nn;
        __syncthreads();
        As[ac4 + 0][arow] = av.x;
        As[ac4 + 1][arow] = av.y;
        As[ac4 + 2][arow] = av.z;
        As[ac4 + 3][arow] = av.w;
        *(float4*)&Bs[brow][bc4] = bv;
        __syncthreads();
#pragma unroll
        for (int kk = 0; kk < 16; kk++) {
            float4 a = *(const float4*)&As[kk][ty * 4];
            float4 b = *(const float4*)&Bs[kk][tx * 4];
            acc[0][0] += a.x * b.x; acc[0][1] += a.x * b.y; acc[0][2] += a.x * b.z; acc[0][3] += a.x * b.w;
            acc[1][0] += a.y * b.x; acc[1][1] += a.y * b.y; acc[1][2] += a.y * b.z; acc[1][3] += a.y * b.w;
            acc[2][0] += a.z * b.x; acc[2][1] += a.z * b.y; acc[2][2] += a.z * b.z; acc[2][3] += a.z * b.w;
            acc[3][0] += a.w * b.x; acc[3][1] += a.w * b.y; acc[3][2] += a.w * b.z; acc[3][3] += a.w * b.w;
        }
    }

    int row = bm + ty * 4, col = bn + tx * 4;
    float4 bb = make_float4(0.f, 0.f, 0.f, 0.f);
    if (bias) bb = *(const float4*)(bias + col);
#pragma unroll
    for (int i = 0; i < 4; i++) {
        float4 cv = make_float4(acc[i][0] + bb.x, acc[i][1] + bb.y,
                                acc[i][2] + bb.z, acc[i][3] + bb.w);
        if (R) {
            float4 rv = *(const float4*)(R + (size_t)(row + i) * Nn + col);
            cv.x += rv.x; cv.y += rv.y; cv.z += rv.z; cv.w += rv.w;
        }
        *(float4*)(C + (size_t)(row + i) * Nn + col) = cv;
    }
}

// ============================================================
// NT GEMM for logits: S[b,i,j] = scale * sum_c q[b,i,c] * k[b,j,c]
// M=N=2048, K=512 fixed; batch via z.
// ============================================================
__global__ void __launch_bounds__(256)
gemm_nt(const float* __restrict__ Q, const float* __restrict__ K,
        float* __restrict__ S) {
    __shared__ float As[16][68];
    __shared__ float Bs[16][68];
    int z = blockIdx.z;
    const float* A  = Q + (size_t)z * Ldim * Cdim;
    const float* Bm = K + (size_t)z * Ldim * Cdim;
    float* C = S + (size_t)z * Ldim * Ldim;

    int bm = blockIdx.y * 64, bn = blockIdx.x * 64;
    int tid = threadIdx.x;
    int tx = tid & 15, ty = tid >> 4;
    int arow = tid >> 2, ac4 = (tid & 3) * 4;

    const float* Aptr = A  + (size_t)(bm + arow) * Cdim + ac4;
    const float* Bptr = Bm + (size_t)(bn + arow) * Cdim + ac4;

    float acc[4][4] = {};

    for (int k0 = 0; k0 < Cdim; k0 += 16) {
        float4 av = *(const float4*)Aptr; Aptr += 16;
        float4 bv = *(const float4*)Bptr; Bptr += 16;
        __syncthreads();
        As[ac4 + 0][arow] = av.x; As[ac4 + 1][arow] = av.y;
        As[ac4 + 2][arow] = av.z; As[ac4 + 3][arow] = av.w;
        Bs[ac4 + 0][arow] = bv.x; Bs[ac4 + 1][arow] = bv.y;
        Bs[ac4 + 2][arow] = bv.z; Bs[ac4 + 3][arow] = bv.w;
        __syncthreads();
#pragma unroll
        for (int kk = 0; kk < 16; kk++) {
            float4 a = *(const float4*)&As[kk][ty * 4];
            float4 b = *(const float4*)&Bs[kk][tx * 4];
            acc[0][0] += a.x * b.x; acc[0][1] += a.x * b.y; acc[0][2] += a.x * b.z; acc[0][3] += a.x * b.w;
            acc[1][0] += a.y * b.x; acc[1][1] += a.y * b.y; acc[1][2] += a.y * b.z; acc[1][3] += a.y * b.w;
            acc[2][0] += a.z * b.x; acc[2][1] += a.z * b.y; acc[2][2] += a.z * b.z; acc[2][3] += a.z * b.w;
            acc[3][0] += a.w * b.x; acc[3][1] += a.w * b.y; acc[3][2] += a.w * b.z; acc[3][3] += a.w * b.w;
        }
    }

    int row = bm + ty * 4, col = bn + tx * 4;
#pragma unroll
    for (int i = 0; i < 4; i++) {
        float4 cv = make_float4(acc[i][0] * SCALE, acc[i][1] * SCALE,
                                acc[i][2] * SCALE, acc[i][3] * SCALE);
        *(float4*)(C + (size_t)(row + i) * Ldim + col) = cv;
    }
}

// ============================================================
// Row softmax over S (in-place): 16384 rows of 2048, 256 threads/row
// ============================================================
__global__ void softmax_k(float* __restrict__ S) {
    float* p = S + (size_t)blockIdx.x * Ldim;
    int t = threadIdx.x;
    float v[8];
    float mx = -1e30f;
#pragma unroll
    for (int i = 0; i < 8; i++) { v[i] = p[t + 256 * i]; mx = fmaxf(mx, v[i]); }
#pragma unroll
    for (int o = 16; o > 0; o >>= 1) mx = fmaxf(mx, __shfl_xor_sync(0xffffffffu, mx, o));
    __shared__ float shm[8], shs[8];
    if ((t & 31) == 0) shm[t >> 5] = mx;
    __syncthreads();
    mx = shm[0];
#pragma unroll
    for (int i = 1; i < 8; i++) mx = fmaxf(mx, shm[i]);
    float s = 0.f;
#pragma unroll
    for (int i = 0; i < 8; i++) { v[i] = __expf(v[i] - mx); s += v[i]; }
#pragma unroll
    for (int o = 16; o > 0; o >>= 1) s += __shfl_xor_sync(0xffffffffu, s, o);
    if ((t & 31) == 0) shs[t >> 5] = s;
    __syncthreads();
    s = 0.f;
#pragma unroll
    for (int i = 0; i < 8; i++) s += shs[i];
    float inv = 1.f / s;
#pragma unroll
    for (int i = 0; i < 8; i++) p[t + 256 * i] = v[i] * inv;
}

// ============================================================
// Host launcher
// ============================================================
extern "C" void kernel_launch(void* const* d_in, const int* in_sizes, int n_in,
                              void* d_out, int out_size) {
    const float* x     = (const float*)d_in[0];
    const float* gamma = (const float*)d_in[1];
    const float* beta  = (const float*)d_in[2];
    const float* wq    = (const float*)d_in[3];
    const float* bq    = (const float*)d_in[4];
    const float* wk    = (const float*)d_in[5];
    const float* bk    = (const float*)d_in[6];
    const float* wv    = (const float*)d_in[7];
    const float* bv    = (const float*)d_in[8];
    const float* wp    = (const float*)d_in[9];
    const float* bp    = (const float*)d_in[10];
    float* out = (float*)d_out;

    float *h, *q, *k, *v, *o, *s;
    cudaGetSymbolAddress((void**)&h, g_h);
    cudaGetSymbolAddress((void**)&q, g_q);
    cudaGetSymbolAddress((void**)&k, g_k);
    cudaGetSymbolAddress((void**)&v, g_v);
    cudaGetSymbolAddress((void**)&o, g_o);
    cudaGetSymbolAddress((void**)&s, g_s);

    // 1) GroupNorm
    gn_stats<<<Bdim * Gdim, 256>>>(x);
    gn_apply<<<(Mdim * Cdim / 4) / 256, 256>>>(
        (const float4*)x, (const float4*)gamma, (const float4*)beta);

    // 2) Q, K, V projections: [16384,512] @ [512,512] + bias
    dim3 gProj(Cdim / 64, Mdim / 64, 1);
    gemm_nn<<<gProj, 256>>>(h, wq, bq, nullptr, q, Cdim, Cdim, 0, 0, 0, 0);
    gemm_nn<<<gProj, 256>>>(h, wk, bk, nullptr, k, Cdim, Cdim, 0, 0, 0, 0);
    gemm_nn<<<gProj, 256>>>(h, wv, bv, nullptr, v, Cdim, Cdim, 0, 0, 0, 0);

    // 3) Logits S = scale * Q K^T  (per batch)
    dim3 gS(Ldim / 64, Ldim / 64, Bdim);
    gemm_nt<<<gS, 256>>>(q, k, s);

    // 4) Row softmax
    softmax_k<<<Mdim, 256>>>(s);

    // 5) O = P @ V  (per batch, K=2048)
    dim3 gPV(Cdim / 64, Ldim / 64, Bdim);
    gemm_nn<<<gPV, 256>>>(s, v, nullptr, nullptr, o, Cdim, Ldim,
                          (long)Ldim * Ldim, (long)Ldim * Cdim, (long)Ldim * Cdim, 0);

    // 6) out = h + (O @ wp + bp)
    gemm_nn<<<gProj, 256>>>(o, wp, bp, h, out, Cdim, Cdim, 0, 0, 0, 0);
}

// round 7
// speedup vs baseline: 2.9851x; 2.9851x over previous
#include <cuda_runtime.h>
#include <math.h>
#include <stdint.h>

#define Bdim 8
#define Ldim 2048
#define Cdim 512
#define Mdim (Bdim*Ldim)          // 16384
#define EPSV 1e-3f
#define SCALE 0.04419417382415922f  // 512^-0.5

// ---- scratch (device globals: allocation-free rule) ----
__device__ float g_h[(size_t)Mdim*Cdim];
__device__ float g_q[(size_t)Mdim*Cdim];
__device__ float g_k[(size_t)Mdim*Cdim];
__device__ float g_v[(size_t)Mdim*Cdim];
__device__ float g_o[(size_t)Mdim*Cdim];
__device__ float g_s[(size_t)Bdim*Ldim*Ldim];   // 134 MB logits
__device__ float g_sum[64];
__device__ float g_ssum[64];

// ============================================================
// helpers
// ============================================================
__device__ __forceinline__ uint32_t f2tf32(float f) {
    uint32_t r;
    asm("cvt.rna.tf32.f32 %0, %1;" : "=r"(r) : "f"(f));
    return r;
}
__device__ __forceinline__ void mma8(float* d, const uint32_t* a, const uint32_t* b) {
    asm volatile(
        "mma.sync.aligned.m16n8k8.row.col.f32.tf32.tf32.f32 "
        "{%0,%1,%2,%3}, {%4,%5,%6,%7}, {%8,%9}, {%0,%1,%2,%3};"
        : "+f"(d[0]), "+f"(d[1]), "+f"(d[2]), "+f"(d[3])
        : "r"(a[0]), "r"(a[1]), "r"(a[2]), "r"(a[3]), "r"(b[0]), "r"(b[1]));
}

// ============================================================
// GroupNorm: zero partials, partial sums, apply
// ============================================================
__global__ void gn_zero() {
    g_sum[threadIdx.x] = 0.f;
    g_ssum[threadIdx.x] = 0.f;
}

__global__ void gn_part(const float* __restrict__ x) {
    int chunk = blockIdx.x;            // 0..15
    int bg = blockIdx.y;               // 0..63
    int b = bg >> 3, g = bg & 7;
    const float* base = x + (size_t)b * Ldim * Cdim + (size_t)chunk * 128 * Cdim + g * 64;
    float s = 0.f, ss = 0.f;
#pragma unroll
    for (int i = 0; i < 8; i++) {
        int idx = threadIdx.x + i * 256;    // 128 rows x 16 float4
        int row = idx >> 4, c4 = idx & 15;
        float4 v = *(const float4*)(base + (size_t)row * Cdim + c4 * 4);
        s += v.x + v.y + v.z + v.w;
        ss += v.x*v.x + v.y*v.y + v.z*v.z + v.w*v.w;
    }
#pragma unroll
    for (int o = 16; o > 0; o >>= 1) {
        s  += __shfl_xor_sync(0xffffffffu, s, o);
        ss += __shfl_xor_sync(0xffffffffu, ss, o);
    }
    __shared__ float sh1[8], sh2[8];
    int w = threadIdx.x >> 5;
    if ((threadIdx.x & 31) == 0) { sh1[w] = s; sh2[w] = ss; }
    __syncthreads();
    if (threadIdx.x == 0) {
        float t1 = 0.f, t2 = 0.f;
#pragma unroll
        for (int i = 0; i < 8; i++) { t1 += sh1[i]; t2 += sh2[i]; }
        atomicAdd(&g_sum[bg], t1);
        atomicAdd(&g_ssum[bg], t2);
    }
}

__global__ void gn_apply(const float4* __restrict__ x,
                         const float4* __restrict__ gamma,
                         const float4* __restrict__ beta) {
    int i = blockIdx.x * 256 + threadIdx.x;
    int e = i * 4;
    int ch = e & (Cdim - 1);
    int row = e >> 9;
    int b = row >> 11;
    int g = ch >> 6;
    const float inv = 1.f / (2048.f * 64.f);
    float m = g_sum[b * 8 + g] * inv;
    float r = rsqrtf(g_ssum[b * 8 + g] * inv - m * m + EPSV);
    float4 xv = x[i];
    float4 ga = gamma[ch >> 2];
    float4 be = beta[ch >> 2];
    float4 hv;
    hv.x = (xv.x - m) * r * ga.x + be.x;
    hv.y = (xv.y - m) * r * ga.y + be.y;
    hv.z = (xv.z - m) * r * ga.z + be.z;
    hv.w = (xv.w - m) * r * ga.w + be.w;
    ((float4*)g_h)[i] = hv;
}

// ============================================================
// tf32 mma.sync GEMM: C[M,N](+bias)(+res) = scl * A @ op(B)
//   CTA tile 128x128, BK=32, 8 warps (4m x 2n), warp tile 32x64
//   smem: tf32-converted tiles, row stride 36 (conflict-free frag LDS)
//   bmode 0: B is [N,K] row-major (k contiguous)   -> direct
//   bmode 1: B is [K,N] row-major (n contiguous)   -> transpose on load
// ============================================================
#define ROWST 36
#define BUF_FLOATS (128*ROWST)           // 4608 floats per tile
#define GEMM_SMEM (4*BUF_FLOATS*4)       // A+B double-buffered: 73728 B

__global__ void __launch_bounds__(256, 2)
gemm_tc(const float* __restrict__ A, const float* __restrict__ B,
        const float* __restrict__ bias, const float* __restrict__ res,
        float* __restrict__ C, int Kn, int Nn, int ldB, int bmode, float scl,
        long sA, long sB, long sC) {
    extern __shared__ float smf[];
    int tid = threadIdx.x, wid = tid >> 5, lid = tid & 31;
    int wm = wid & 3, wn = wid >> 2;
    int z = blockIdx.z;
    A += (size_t)z * sA;
    B += (size_t)z * sB;
    C += (size_t)z * sC;
    int bm = blockIdx.y * 128, bn = blockIdx.x * 128;

    float acc[2][8][4];
#pragma unroll
    for (int mt = 0; mt < 2; mt++)
#pragma unroll
        for (int nt = 0; nt < 8; nt++)
#pragma unroll
            for (int i = 0; i < 4; i++) acc[mt][nt][i] = 0.f;

    float4 pfA[4];
    float pfB[16];

    const int fr = tid >> 3, fq = tid & 7;          // tile loader coords
    const int tn = tid & 127, tk = tid >> 7;        // transpose loader coords

    // ---- prefetch chunk 0 ----
    {
#pragma unroll
        for (int i = 0; i < 4; i++) {
            int r = fr + i * 32;
            pfA[i] = *(const float4*)(A + (size_t)(bm + r) * Kn + fq * 4);
        }
        if (bmode == 0) {
#pragma unroll
            for (int i = 0; i < 4; i++) {
                int r = fr + i * 32;
                *(float4*)(pfB + i * 4) =
                    *(const float4*)(B + (size_t)(bn + r) * ldB + fq * 4);
            }
        } else {
#pragma unroll
            for (int i = 0; i < 16; i++)
                pfB[i] = B[(size_t)(tk + i * 2) * ldB + bn + tn];
        }
    }

    const int g = lid >> 2, c = lid & 3;
    int nch = Kn >> 5;

    for (int kc = 0; kc < nch; kc++) {
        float* Asb = smf + (kc & 1) * (2 * BUF_FLOATS);
        float* Bsb = Asb + BUF_FLOATS;
        uint32_t* Au = (uint32_t*)Asb;
        uint32_t* Bu = (uint32_t*)Bsb;

        // ---- STS (tf32 convert) ----
#pragma unroll
        for (int i = 0; i < 4; i++) {
            int r = fr + i * 32;
            uint32_t* p = Au + r * ROWST + fq * 4;
            p[0] = f2tf32(pfA[i].x); p[1] = f2tf32(pfA[i].y);
            p[2] = f2tf32(pfA[i].z); p[3] = f2tf32(pfA[i].w);
        }
        if (bmode == 0) {
#pragma unroll
            for (int i = 0; i < 4; i++) {
                int r = fr + i * 32;
                uint32_t* p = Bu + r * ROWST + fq * 4;
                p[0] = f2tf32(pfB[4*i+0]); p[1] = f2tf32(pfB[4*i+1]);
                p[2] = f2tf32(pfB[4*i+2]); p[3] = f2tf32(pfB[4*i+3]);
            }
        } else {
#pragma unroll
            for (int i = 0; i < 16; i++)
                Bu[tn * ROWST + tk + i * 2] = f2tf32(pfB[i]);
        }
        __syncthreads();

        // ---- prefetch next chunk ----
        if (kc + 1 < nch) {
            int k0 = (kc + 1) << 5;
#pragma unroll
            for (int i = 0; i < 4; i++) {
                int r = fr + i * 32;
                pfA[i] = *(const float4*)(A + (size_t)(bm + r) * Kn + k0 + fq * 4);
            }
            if (bmode == 0) {
#pragma unroll
                for (int i = 0; i < 4; i++) {
                    int r = fr + i * 32;
                    *(float4*)(pfB + i * 4) =
                        *(const float4*)(B + (size_t)(bn + r) * ldB + k0 + fq * 4);
                }
            } else {
#pragma unroll
                for (int i = 0; i < 16; i++)
                    pfB[i] = B[(size_t)(k0 + tk + i * 2) * ldB + bn + tn];
            }
        }

        // ---- compute: 4 k-slices of 8 ----
#pragma unroll
        for (int s = 0; s < 4; s++) {
            uint32_t af[2][4];
#pragma unroll
            for (int mt = 0; mt < 2; mt++) {
                int r0 = wm * 32 + mt * 16 + g;
                af[mt][0] = Au[r0 * ROWST + 8 * s + c];
                af[mt][1] = Au[(r0 + 8) * ROWST + 8 * s + c];
                af[mt][2] = Au[r0 * ROWST + 8 * s + c + 4];
                af[mt][3] = Au[(r0 + 8) * ROWST + 8 * s + c + 4];
            }
            uint32_t bf[8][2];
#pragma unroll
            for (int nt = 0; nt < 8; nt++) {
                int n0 = wn * 64 + nt * 8 + g;
                bf[nt][0] = Bu[n0 * ROWST + 8 * s + c];
                bf[nt][1] = Bu[n0 * ROWST + 8 * s + c + 4];
            }
#pragma unroll
            for (int mt = 0; mt < 2; mt++)
#pragma unroll
                for (int nt = 0; nt < 8; nt++)
                    mma8(acc[mt][nt], af[mt], bf[nt]);
        }
        // single barrier per iter: next STS targets the other buffer,
        // whose last readers finished before the sync above.
    }

    // ---- epilogue ----
    int c2 = (lid & 3) * 2;
#pragma unroll
    for (int mt = 0; mt < 2; mt++) {
        int row0 = bm + wm * 32 + mt * 16 + g;
#pragma unroll
        for (int nt = 0; nt < 8; nt++) {
            int col = bn + wn * 64 + nt * 8 + c2;
            float b0 = 0.f, b1 = 0.f;
            if (bias) { b0 = __ldg(bias + col); b1 = __ldg(bias + col + 1); }
            float v00 = acc[mt][nt][0] * scl + b0;
            float v01 = acc[mt][nt][1] * scl + b1;
            float v10 = acc[mt][nt][2] * scl + b0;
            float v11 = acc[mt][nt][3] * scl + b1;
            if (res) {
                const float* r0p = res + (size_t)row0 * Nn + col;
                const float* r1p = res + (size_t)(row0 + 8) * Nn + col;
                v00 += r0p[0]; v01 += r0p[1];
                v10 += r1p[0]; v11 += r1p[1];
            }
            float2 o0 = make_float2(v00, v01);
            float2 o1 = make_float2(v10, v11);
            *(float2*)(C + (size_t)row0 * Nn + col) = o0;
            *(float2*)(C + (size_t)(row0 + 8) * Nn + col) = o1;
        }
    }
}

// ============================================================
// Row softmax over S (in-place): 16384 rows of 2048
// ============================================================
__global__ void softmax_k(float* __restrict__ S) {
    float* p = S + (size_t)blockIdx.x * Ldim;
    int t = threadIdx.x;
    float v[8];
    float mx = -1e30f;
#pragma unroll
    for (int i = 0; i < 8; i++) { v[i] = p[t + 256 * i]; mx = fmaxf(mx, v[i]); }
#pragma unroll
    for (int o = 16; o > 0; o >>= 1) mx = fmaxf(mx, __shfl_xor_sync(0xffffffffu, mx, o));
    __shared__ float shm[8], shs[8];
    if ((t & 31) == 0) shm[t >> 5] = mx;
    __syncthreads();
    mx = shm[0];
#pragma unroll
    for (int i = 1; i < 8; i++) mx = fmaxf(mx, shm[i]);
    float s = 0.f;
#pragma unroll
    for (int i = 0; i < 8; i++) { v[i] = __expf(v[i] - mx); s += v[i]; }
#pragma unroll
    for (int o = 16; o > 0; o >>= 1) s += __shfl_xor_sync(0xffffffffu, s, o);
    if ((t & 31) == 0) shs[t >> 5] = s;
    __syncthreads();
    s = 0.f;
#pragma unroll
    for (int i = 0; i < 8; i++) s += shs[i];
    float inv = 1.f / s;
#pragma unroll
    for (int i = 0; i < 8; i++) p[t + 256 * i] = v[i] * inv;
}

// ============================================================
// Host launcher
// ============================================================
extern "C" void kernel_launch(void* const* d_in, const int* in_sizes, int n_in,
                              void* d_out, int out_size) {
    const float* x     = (const float*)d_in[0];
    const float* gamma = (const float*)d_in[1];
    const float* beta  = (const float*)d_in[2];
    const float* wq    = (const float*)d_in[3];
    const float* bq    = (const float*)d_in[4];
    const float* wk    = (const float*)d_in[5];
    const float* bk    = (const float*)d_in[6];
    const float* wv    = (const float*)d_in[7];
    const float* bv    = (const float*)d_in[8];
    const float* wp    = (const float*)d_in[9];
    const float* bp    = (const float*)d_in[10];
    float* out = (float*)d_out;

    float *h, *q, *k, *v, *o, *s;
    cudaGetSymbolAddress((void**)&h, g_h);
    cudaGetSymbolAddress((void**)&q, g_q);
    cudaGetSymbolAddress((void**)&k, g_k);
    cudaGetSymbolAddress((void**)&v, g_v);
    cudaGetSymbolAddress((void**)&o, g_o);
    cudaGetSymbolAddress((void**)&s, g_s);

    static int smem_set = 0;
    if (!smem_set) {
        cudaFuncSetAttribute(gemm_tc, cudaFuncAttributeMaxDynamicSharedMemorySize, GEMM_SMEM);
        smem_set = 1;
    }

    const long LC = (long)Ldim * Cdim;
    const long LL = (long)Ldim * Ldim;

    // 1) GroupNorm
    gn_zero<<<1, 64>>>();
    gn_part<<<dim3(16, 64), 256>>>(x);
    gn_apply<<<(Mdim * Cdim / 4) / 256, 256>>>(
        (const float4*)x, (const float4*)gamma, (const float4*)beta);

    // 2) Q, K, V projections: [16384,512] @ [512,512] + bias (B transposed)
    dim3 gProj(Cdim / 128, Mdim / 128, 1);
    gemm_tc<<<gProj, 256, GEMM_SMEM>>>(h, wq, bq, nullptr, q, Cdim, Cdim, Cdim, 1, 1.f, 0, 0, 0);
    gemm_tc<<<gProj, 256, GEMM_SMEM>>>(h, wk, bk, nullptr, k, Cdim, Cdim, Cdim, 1, 1.f, 0, 0, 0);
    gemm_tc<<<gProj, 256, GEMM_SMEM>>>(h, wv, bv, nullptr, v, Cdim, Cdim, Cdim, 1, 1.f, 0, 0, 0);

    // 3) Logits S = scale * Q K^T (per batch, B direct)
    dim3 gS(Ldim / 128, Ldim / 128, Bdim);
    gemm_tc<<<gS, 256, GEMM_SMEM>>>(q, k, nullptr, nullptr, s, Cdim, Ldim, Cdim, 0, SCALE, LC, LC, LL);

    // 4) Row softmax
    softmax_k<<<Mdim, 256>>>(s);

    // 5) O = P @ V (per batch, K=2048, B transposed)
    dim3 gPV(Cdim / 128, Ldim / 128, Bdim);
    gemm_tc<<<gPV, 256, GEMM_SMEM>>>(s, v, nullptr, nullptr, o, Ldim, Cdim, Cdim, 1, 1.f, LL, LC, LC);

    // 6) out = h + (O @ wp + bp)
    gemm_tc<<<gProj, 256, GEMM_SMEM>>>(o, wp, bp, h, out, Cdim, Cdim, Cdim, 1, 1.f, 0, 0, 0);
}

// round 8
// speedup vs baseline: 3.6173x; 1.2118x over previous
#include <cuda_runtime.h>
#include <math.h>
#include <stdint.h>

#define Bdim 8
#define Ldim 2048
#define Cdim 512
#define Mdim (Bdim*Ldim)          // 16384
#define EPSV 1e-3f
#define SCALE 0.04419417382415922f  // 512^-0.5

// ---- scratch (device globals: allocation-free rule) ----
__device__ float g_h[(size_t)Mdim*Cdim];
__device__ float g_q[(size_t)Mdim*Cdim];
__device__ float g_k[(size_t)Mdim*Cdim];
__device__ float g_v[(size_t)Mdim*Cdim];
__device__ float g_o[(size_t)Mdim*Cdim];
__device__ float g_s[(size_t)Bdim*Ldim*Ldim];   // 134 MB logits
__device__ float g_sum[64];
__device__ float g_ssum[64];

// ============================================================
// helpers
// ============================================================
__device__ __forceinline__ uint32_t smem_u32(const void* p) {
    uint32_t a;
    asm("{ .reg .u64 t; cvta.to.shared.u64 t, %1; cvt.u32.u64 %0, t; }"
        : "=r"(a) : "l"(p));
    return a;
}
__device__ __forceinline__ void cpa16(uint32_t dst, const void* src) {
    asm volatile("cp.async.cg.shared.global [%0], [%1], 16;"
                 :: "r"(dst), "l"(src) : "memory");
}
__device__ __forceinline__ void cpa_commit() {
    asm volatile("cp.async.commit_group;" ::: "memory");
}
template<int N> __device__ __forceinline__ void cpa_wait() {
    asm volatile("cp.async.wait_group %0;" :: "n"(N) : "memory");
}
__device__ __forceinline__ void mma8(float* d, const uint32_t* a, const uint32_t* b) {
    asm volatile(
        "mma.sync.aligned.m16n8k8.row.col.f32.tf32.tf32.f32 "
        "{%0,%1,%2,%3}, {%4,%5,%6,%7}, {%8,%9}, {%0,%1,%2,%3};"
        : "+f"(d[0]), "+f"(d[1]), "+f"(d[2]), "+f"(d[3])
        : "r"(a[0]), "r"(a[1]), "r"(a[2]), "r"(a[3]), "r"(b[0]), "r"(b[1]));
}

// ============================================================
// GroupNorm: zero partials, partial sums, apply
// ============================================================
__global__ void gn_zero() {
    g_sum[threadIdx.x] = 0.f;
    g_ssum[threadIdx.x] = 0.f;
}

__global__ void gn_part(const float* __restrict__ x) {
    int chunk = blockIdx.x;            // 0..15
    int bg = blockIdx.y;               // 0..63
    int b = bg >> 3, g = bg & 7;
    const float* base = x + (size_t)b * Ldim * Cdim + (size_t)chunk * 128 * Cdim + g * 64;
    float s = 0.f, ss = 0.f;
#pragma unroll
    for (int i = 0; i < 8; i++) {
        int idx = threadIdx.x + i * 256;    // 128 rows x 16 float4
        int row = idx >> 4, c4 = idx & 15;
        float4 v = *(const float4*)(base + (size_t)row * Cdim + c4 * 4);
        s += v.x + v.y + v.z + v.w;
        ss += v.x*v.x + v.y*v.y + v.z*v.z + v.w*v.w;
    }
#pragma unroll
    for (int o = 16; o > 0; o >>= 1) {
        s  += __shfl_xor_sync(0xffffffffu, s, o);
        ss += __shfl_xor_sync(0xffffffffu, ss, o);
    }
    __shared__ float sh1[8], sh2[8];
    int w = threadIdx.x >> 5;
    if ((threadIdx.x & 31) == 0) { sh1[w] = s; sh2[w] = ss; }
    __syncthreads();
    if (threadIdx.x == 0) {
        float t1 = 0.f, t2 = 0.f;
#pragma unroll
        for (int i = 0; i < 8; i++) { t1 += sh1[i]; t2 += sh2[i]; }
        atomicAdd(&g_sum[bg], t1);
        atomicAdd(&g_ssum[bg], t2);
    }
}

__global__ void gn_apply(const float4* __restrict__ x,
                         const float4* __restrict__ gamma,
                         const float4* __restrict__ beta) {
    int i = blockIdx.x * 256 + threadIdx.x;
    int e = i * 4;
    int ch = e & (Cdim - 1);
    int row = e >> 9;
    int b = row >> 11;
    int g = ch >> 6;
    const float inv = 1.f / (2048.f * 64.f);
    float m = g_sum[b * 8 + g] * inv;
    float r = rsqrtf(g_ssum[b * 8 + g] * inv - m * m + EPSV);
    float4 xv = x[i];
    float4 ga = gamma[ch >> 2];
    float4 be = beta[ch >> 2];
    float4 hv;
    hv.x = (xv.x - m) * r * ga.x + be.x;
    hv.y = (xv.y - m) * r * ga.y + be.y;
    hv.z = (xv.z - m) * r * ga.z + be.z;
    hv.w = (xv.w - m) * r * ga.w + be.w;
    ((float4*)g_h)[i] = hv;
}

// ============================================================
// tf32 mma.sync GEMM, cp.async double-buffered:
//   C[M,N](+bias)(+res) = scl * A @ op(B)
//   CTA tile 128x128, BK=32, 8 warps (4m x 2n), warp tile 32x64
//   BMODE 0: B is [N,K] row-major -> smem [n][k], stride 36
//   BMODE 1: B is [K,N] row-major -> smem [k][n], stride 136 (no transpose)
// ============================================================
#define AST 36                            // A (and BMODE0 B) row stride, floats
#define BST1 136                          // BMODE1 B row stride, floats
#define STAGE_FLOATS (2*4608)             // A tile 128*36=4608 + B tile slot 4608
#define GEMM_SMEM (2*STAGE_FLOATS*4)      // 73728 B, 2 stages

template<int BMODE>
__global__ void __launch_bounds__(256, 2)
gemm_tc(const float* __restrict__ A, const float* __restrict__ B,
        const float* __restrict__ bias, const float* __restrict__ res,
        float* __restrict__ C, int Kn, int Nn, int ldB, float scl,
        long sA, long sB, long sC) {
    extern __shared__ float smf[];
    const uint32_t sb = smem_u32(smf);
    int tid = threadIdx.x, wid = tid >> 5, lid = tid & 31;
    int wm = wid & 3, wn = wid >> 2;
    int z = blockIdx.z;
    A += (size_t)z * sA;
    B += (size_t)z * sB;
    C += (size_t)z * sC;
    int bm = blockIdx.y * 128, bn = blockIdx.x * 128;

    float acc[2][8][4];
#pragma unroll
    for (int mt = 0; mt < 2; mt++)
#pragma unroll
        for (int nt = 0; nt < 8; nt++)
#pragma unroll
            for (int i = 0; i < 4; i++) acc[mt][nt][i] = 0.f;

    const int fr = tid >> 3, fq = tid & 7;          // 128x32 tile loader
    const int br1 = tid >> 5, bc1 = tid & 31;       // BMODE1 32x128 loader

    const float* Abase = A + (size_t)bm * Kn;       // + r*Kn + k0 + fq*4
    const float* Bbase0 = B + (size_t)bn * ldB;     // BMODE0
    const float* Bbase1 = B + bn;                   // BMODE1

    // issue one stage of cp.async loads
    auto issue = [&](int kc) {
        int k0 = kc << 5;
        uint32_t as = sb + (kc & 1) * (STAGE_FLOATS * 4);
        uint32_t bs = as + 4608 * 4;
#pragma unroll
        for (int i = 0; i < 4; i++) {
            int r = fr + i * 32;
            cpa16(as + (r * AST + fq * 4) * 4,
                  Abase + (size_t)r * Kn + k0 + fq * 4);
        }
        if (BMODE == 0) {
#pragma unroll
            for (int i = 0; i < 4; i++) {
                int r = fr + i * 32;
                cpa16(bs + (r * AST + fq * 4) * 4,
                      Bbase0 + (size_t)r * ldB + k0 + fq * 4);
            }
        } else {
#pragma unroll
            for (int i = 0; i < 4; i++) {
                int r = br1 + i * 8;
                cpa16(bs + (r * BST1 + bc1 * 4) * 4,
                      Bbase1 + (size_t)(k0 + r) * ldB + bc1 * 4);
            }
        }
        cpa_commit();
    };

    int nch = Kn >> 5;
    issue(0);

    const int g = lid >> 2, c = lid & 3;

    for (int kc = 0; kc < nch; kc++) {
        if (kc + 1 < nch) { issue(kc + 1); cpa_wait<1>(); }
        else cpa_wait<0>();
        __syncthreads();

        const uint32_t* Au = (const uint32_t*)(smf + (kc & 1) * STAGE_FLOATS);
        const uint32_t* Bu = Au + 4608;

#pragma unroll
        for (int s = 0; s < 4; s++) {
            uint32_t af[2][4];
#pragma unroll
            for (int mt = 0; mt < 2; mt++) {
                int r0 = wm * 32 + mt * 16 + g;
                af[mt][0] = Au[r0 * AST + 8 * s + c];
                af[mt][1] = Au[(r0 + 8) * AST + 8 * s + c];
                af[mt][2] = Au[r0 * AST + 8 * s + c + 4];
                af[mt][3] = Au[(r0 + 8) * AST + 8 * s + c + 4];
            }
            uint32_t bf[8][2];
#pragma unroll
            for (int nt = 0; nt < 8; nt++) {
                int n0 = wn * 64 + nt * 8 + g;
                if (BMODE == 0) {
                    bf[nt][0] = Bu[n0 * AST + 8 * s + c];
                    bf[nt][1] = Bu[n0 * AST + 8 * s + c + 4];
                } else {
                    bf[nt][0] = Bu[(8 * s + c) * BST1 + n0];
                    bf[nt][1] = Bu[(8 * s + c + 4) * BST1 + n0];
                }
            }
#pragma unroll
            for (int mt = 0; mt < 2; mt++)
#pragma unroll
                for (int nt = 0; nt < 8; nt++)
                    mma8(acc[mt][nt], af[mt], bf[nt]);
        }
        __syncthreads();
    }

    // ---- epilogue ----
    int c2 = (lid & 3) * 2;
#pragma unroll
    for (int mt = 0; mt < 2; mt++) {
        int row0 = bm + wm * 32 + mt * 16 + g;
#pragma unroll
        for (int nt = 0; nt < 8; nt++) {
            int col = bn + wn * 64 + nt * 8 + c2;
            float b0 = 0.f, b1 = 0.f;
            if (bias) { b0 = __ldg(bias + col); b1 = __ldg(bias + col + 1); }
            float v00 = acc[mt][nt][0] * scl + b0;
            float v01 = acc[mt][nt][1] * scl + b1;
            float v10 = acc[mt][nt][2] * scl + b0;
            float v11 = acc[mt][nt][3] * scl + b1;
            if (res) {
                const float* r0p = res + (size_t)row0 * Nn + col;
                const float* r1p = res + (size_t)(row0 + 8) * Nn + col;
                v00 += r0p[0]; v01 += r0p[1];
                v10 += r1p[0]; v11 += r1p[1];
            }
            *(float2*)(C + (size_t)row0 * Nn + col) = make_float2(v00, v01);
            *(float2*)(C + (size_t)(row0 + 8) * Nn + col) = make_float2(v10, v11);
        }
    }
}

// ============================================================
// Row softmax over S (in-place): 16384 rows of 2048
// ============================================================
__global__ void softmax_k(float* __restrict__ S) {
    float* p = S + (size_t)blockIdx.x * Ldim;
    int t = threadIdx.x;
    float v[8];
    float mx = -1e30f;
#pragma unroll
    for (int i = 0; i < 8; i++) { v[i] = p[t + 256 * i]; mx = fmaxf(mx, v[i]); }
#pragma unroll
    for (int o = 16; o > 0; o >>= 1) mx = fmaxf(mx, __shfl_xor_sync(0xffffffffu, mx, o));
    __shared__ float shm[8], shs[8];
    if ((t & 31) == 0) shm[t >> 5] = mx;
    __syncthreads();
    mx = shm[0];
#pragma unroll
    for (int i = 1; i < 8; i++) mx = fmaxf(mx, shm[i]);
    float s = 0.f;
#pragma unroll
    for (int i = 0; i < 8; i++) { v[i] = __expf(v[i] - mx); s += v[i]; }
#pragma unroll
    for (int o = 16; o > 0; o >>= 1) s += __shfl_xor_sync(0xffffffffu, s, o);
    if ((t & 31) == 0) shs[t >> 5] = s;
    __syncthreads();
    s = 0.f;
#pragma unroll
    for (int i = 0; i < 8; i++) s += shs[i];
    float inv = 1.f / s;
#pragma unroll
    for (int i = 0; i < 8; i++) p[t + 256 * i] = v[i] * inv;
}

// ============================================================
// Host launcher
// ============================================================
extern "C" void kernel_launch(void* const* d_in, const int* in_sizes, int n_in,
                              void* d_out, int out_size) {
    const float* x     = (const float*)d_in[0];
    const float* gamma = (const float*)d_in[1];
    const float* beta  = (const float*)d_in[2];
    const float* wq    = (const float*)d_in[3];
    const float* bq    = (const float*)d_in[4];
    const float* wk    = (const float*)d_in[5];
    const float* bk    = (const float*)d_in[6];
    const float* wv    = (const float*)d_in[7];
    const float* bv    = (const float*)d_in[8];
    const float* wp    = (const float*)d_in[9];
    const float* bp    = (const float*)d_in[10];
    float* out = (float*)d_out;

    float *h, *q, *k, *v, *o, *s;
    cudaGetSymbolAddress((void**)&h, g_h);
    cudaGetSymbolAddress((void**)&q, g_q);
    cudaGetSymbolAddress((void**)&k, g_k);
    cudaGetSymbolAddress((void**)&v, g_v);
    cudaGetSymbolAddress((void**)&o, g_o);
    cudaGetSymbolAddress((void**)&s, g_s);

    static int smem_set = 0;
    if (!smem_set) {
        cudaFuncSetAttribute(gemm_tc<0>, cudaFuncAttributeMaxDynamicSharedMemorySize, GEMM_SMEM);
        cudaFuncSetAttribute(gemm_tc<1>, cudaFuncAttributeMaxDynamicSharedMemorySize, GEMM_SMEM);
        smem_set = 1;
    }

    const long LC = (long)Ldim * Cdim;
    const long LL = (long)Ldim * Ldim;

    // 1) GroupNorm
    gn_zero<<<1, 64>>>();
    gn_part<<<dim3(16, 64), 256>>>(x);
    gn_apply<<<(Mdim * Cdim / 4) / 256, 256>>>(
        (const float4*)x, (const float4*)gamma, (const float4*)beta);

    // 2) Q, K, V projections: [16384,512] @ [512,512] + bias (B is [K,N])
    dim3 gProj(Cdim / 128, Mdim / 128, 1);
    gemm_tc<1><<<gProj, 256, GEMM_SMEM>>>(h, wq, bq, nullptr, q, Cdim, Cdim, Cdim, 1.f, 0, 0, 0);
    gemm_tc<1><<<gProj, 256, GEMM_SMEM>>>(h, wk, bk, nullptr, k, Cdim, Cdim, Cdim, 1.f, 0, 0, 0);
    gemm_tc<1><<<gProj, 256, GEMM_SMEM>>>(h, wv, bv, nullptr, v, Cdim, Cdim, Cdim, 1.f, 0, 0, 0);

    // 3) Logits S = scale * Q K^T (per batch, B is [N,K])
    dim3 gS(Ldim / 128, Ldim / 128, Bdim);
    gemm_tc<0><<<gS, 256, GEMM_SMEM>>>(q, k, nullptr, nullptr, s, Cdim, Ldim, Cdim, SCALE, LC, LC, LL);

    // 4) Row softmax
    softmax_k<<<Mdim, 256>>>(s);

    // 5) O = P @ V (per batch, K=2048, B is [K,N])
    dim3 gPV(Cdim / 128, Ldim / 128, Bdim);
    gemm_tc<1><<<gPV, 256, GEMM_SMEM>>>(s, v, nullptr, nullptr, o, Ldim, Cdim, Cdim, 1.f, LL, LC, LC);

    // 6) out = h + (O @ wp + bp)
    gemm_tc<1><<<gProj, 256, GEMM_SMEM>>>(o, wp, bp, h, out, Cdim, Cdim, Cdim, 1.f, 0, 0, 0);
}

// round 10
// speedup vs baseline: 5.1976x; 1.4369x over previous
#include <cuda_runtime.h>
#include <cuda_bf16.h>
#include <math.h>
#include <stdint.h>

#define Bdim 8
#define Ldim 2048
#define Cdim 512
#define Mdim (Bdim*Ldim)          // 16384
#define EPSV 1e-3f
#define SCALE 0.04419417382415922f  // 512^-0.5

// ---- scratch (device globals: allocation-free rule) ----
__device__ float g_h[(size_t)Mdim*Cdim];
__device__ float g_o[(size_t)Mdim*Cdim];
__device__ __nv_bfloat16 g_qb[(size_t)Mdim*Cdim];
__device__ __nv_bfloat16 g_kb[(size_t)Mdim*Cdim];
__device__ __nv_bfloat16 g_vT[(size_t)Mdim*Cdim];          // [b][c][l]
__device__ __nv_bfloat16 g_sb[(size_t)Bdim*Ldim*Ldim];     // 67 MB P (unnormalized)
__device__ float g_rowsum[Mdim];
__device__ float g_sum[64];
__device__ float g_ssum[64];

// ============================================================
// helpers
// ============================================================
__device__ __forceinline__ uint32_t smem_u32(const void* p) {
    uint32_t a;
    asm("{ .reg .u64 t; cvta.to.shared.u64 t, %1; cvt.u32.u64 %0, t; }"
        : "=r"(a) : "l"(p));
    return a;
}
__device__ __forceinline__ void cpa16(uint32_t dst, const void* src) {
    asm volatile("cp.async.cg.shared.global [%0], [%1], 16;"
                 :: "r"(dst), "l"(src) : "memory");
}
__device__ __forceinline__ void cpa_commit() {
    asm volatile("cp.async.commit_group;" ::: "memory");
}
template<int N> __device__ __forceinline__ void cpa_wait() {
    asm volatile("cp.async.wait_group %0;" :: "n"(N) : "memory");
}
__device__ __forceinline__ void mma8(float* d, const uint32_t* a, const uint32_t* b) {
    asm volatile(
        "mma.sync.aligned.m16n8k8.row.col.f32.tf32.tf32.f32 "
        "{%0,%1,%2,%3}, {%4,%5,%6,%7}, {%8,%9}, {%0,%1,%2,%3};"
        : "+f"(d[0]), "+f"(d[1]), "+f"(d[2]), "+f"(d[3])
        : "r"(a[0]), "r"(a[1]), "r"(a[2]), "r"(a[3]), "r"(b[0]), "r"(b[1]));
}
__device__ __forceinline__ void mma16(float* d, const uint32_t* a, const uint32_t* b) {
    asm volatile(
        "mma.sync.aligned.m16n8k16.row.col.f32.bf16.bf16.f32 "
        "{%0,%1,%2,%3}, {%4,%5,%6,%7}, {%8,%9}, {%0,%1,%2,%3};"
        : "+f"(d[0]), "+f"(d[1]), "+f"(d[2]), "+f"(d[3])
        : "r"(a[0]), "r"(a[1]), "r"(a[2]), "r"(a[3]), "r"(b[0]), "r"(b[1]));
}

// ============================================================
// GroupNorm + rowsum zero
// ============================================================
__global__ void gn_zero() {
    g_sum[threadIdx.x] = 0.f;
    g_ssum[threadIdx.x] = 0.f;
}
__global__ void rs_zero() {
    g_rowsum[blockIdx.x * 256 + threadIdx.x] = 0.f;
}

__global__ void gn_part(const float* __restrict__ x) {
    int chunk = blockIdx.x;            // 0..15
    int bg = blockIdx.y;               // 0..63
    int b = bg >> 3, g = bg & 7;
    const float* base = x + (size_t)b * Ldim * Cdim + (size_t)chunk * 128 * Cdim + g * 64;
    float s = 0.f, ss = 0.f;
#pragma unroll
    for (int i = 0; i < 8; i++) {
        int idx = threadIdx.x + i * 256;
        int row = idx >> 4, c4 = idx & 15;
        float4 v = *(const float4*)(base + (size_t)row * Cdim + c4 * 4);
        s += v.x + v.y + v.z + v.w;
        ss += v.x*v.x + v.y*v.y + v.z*v.z + v.w*v.w;
    }
#pragma unroll
    for (int o = 16; o > 0; o >>= 1) {
        s  += __shfl_xor_sync(0xffffffffu, s, o);
        ss += __shfl_xor_sync(0xffffffffu, ss, o);
    }
    __shared__ float sh1[8], sh2[8];
    int w = threadIdx.x >> 5;
    if ((threadIdx.x & 31) == 0) { sh1[w] = s; sh2[w] = ss; }
    __syncthreads();
    if (threadIdx.x == 0) {
        float t1 = 0.f, t2 = 0.f;
#pragma unroll
        for (int i = 0; i < 8; i++) { t1 += sh1[i]; t2 += sh2[i]; }
        atomicAdd(&g_sum[bg], t1);
        atomicAdd(&g_ssum[bg], t2);
    }
}

__global__ void gn_apply(const float4* __restrict__ x,
                         const float4* __restrict__ gamma,
                         const float4* __restrict__ beta) {
    int i = blockIdx.x * 256 + threadIdx.x;
    int e = i * 4;
    int ch = e & (Cdim - 1);
    int row = e >> 9;
    int b = row >> 11;
    int g = ch >> 6;
    const float inv = 1.f / (2048.f * 64.f);
    float m = g_sum[b * 8 + g] * inv;
    float r = rsqrtf(g_ssum[b * 8 + g] * inv - m * m + EPSV);
    float4 xv = x[i];
    float4 ga = gamma[ch >> 2];
    float4 be = beta[ch >> 2];
    float4 hv;
    hv.x = (xv.x - m) * r * ga.x + be.x;
    hv.y = (xv.y - m) * r * ga.y + be.y;
    hv.z = (xv.z - m) * r * ga.z + be.z;
    hv.w = (xv.w - m) * r * ga.w + be.w;
    ((float4*)g_h)[i] = hv;
}

// ============================================================
// tf32 GEMM (proj / out-proj): C = A[M,K] @ B[K,N] + bias (+res)
//   A fp32 k-contig, B fp32 [K,N] n-contig. CTA 128x128, BK=32.
//   EPI 0: fp32 out + res      (out-proj)
//   EPI 1: bf16 out            (q, k)
//   EPI 2: bf16 transposed out (v -> vT[b][c][l])
// ============================================================
#define AST 36
#define BST1 136
#define STAGE_FLOATS (2*4608)
#define GEMM_SMEM (2*STAGE_FLOATS*4)      // 73728 B

template<int EPI>
__global__ void __launch_bounds__(256, 2)
gemm_tf32(const float* __restrict__ A, const float* __restrict__ B,
          const float* __restrict__ bias, const float* __restrict__ res,
          void* __restrict__ Cv, int Kn, int Nn, int ldB) {
    extern __shared__ float smf[];
    const uint32_t sb = smem_u32(smf);
    int tid = threadIdx.x, wid = tid >> 5, lid = tid & 31;
    int wm = wid & 3, wn = wid >> 2;
    int bm = blockIdx.y * 128, bn = blockIdx.x * 128;

    float acc[2][8][4];
#pragma unroll
    for (int mt = 0; mt < 2; mt++)
#pragma unroll
        for (int nt = 0; nt < 8; nt++)
#pragma unroll
            for (int i = 0; i < 4; i++) acc[mt][nt][i] = 0.f;

    const int fr = tid >> 3, fq = tid & 7;
    const int br1 = tid >> 5, bc1 = tid & 31;
    const float* Abase = A + (size_t)bm * Kn;
    const float* Bbase = B + bn;

    auto issue = [&](int kc) {
        int k0 = kc << 5;
        uint32_t as = sb + (kc & 1) * (STAGE_FLOATS * 4);
        uint32_t bs = as + 4608 * 4;
#pragma unroll
        for (int i = 0; i < 4; i++) {
            int r = fr + i * 32;
            cpa16(as + (r * AST + fq * 4) * 4, Abase + (size_t)r * Kn + k0 + fq * 4);
        }
#pragma unroll
        for (int i = 0; i < 4; i++) {
            int r = br1 + i * 8;
            cpa16(bs + (r * BST1 + bc1 * 4) * 4, Bbase + (size_t)(k0 + r) * ldB + bc1 * 4);
        }
        cpa_commit();
    };

    int nch = Kn >> 5;
    issue(0);
    const int g = lid >> 2, c = lid & 3;

    for (int kc = 0; kc < nch; kc++) {
        if (kc + 1 < nch) { issue(kc + 1); cpa_wait<1>(); }
        else cpa_wait<0>();
        __syncthreads();
        const uint32_t* Au = (const uint32_t*)(smf + (kc & 1) * STAGE_FLOATS);
        const uint32_t* Bu = Au + 4608;
#pragma unroll
        for (int s = 0; s < 4; s++) {
            uint32_t af[2][4];
#pragma unroll
            for (int mt = 0; mt < 2; mt++) {
                int r0 = wm * 32 + mt * 16 + g;
                af[mt][0] = Au[r0 * AST + 8 * s + c];
                af[mt][1] = Au[(r0 + 8) * AST + 8 * s + c];
                af[mt][2] = Au[r0 * AST + 8 * s + c + 4];
                af[mt][3] = Au[(r0 + 8) * AST + 8 * s + c + 4];
            }
            uint32_t bf[8][2];
#pragma unroll
            for (int nt = 0; nt < 8; nt++) {
                int n0 = wn * 64 + nt * 8 + g;
                bf[nt][0] = Bu[(8 * s + c) * BST1 + n0];
                bf[nt][1] = Bu[(8 * s + c + 4) * BST1 + n0];
            }
#pragma unroll
            for (int mt = 0; mt < 2; mt++)
#pragma unroll
                for (int nt = 0; nt < 8; nt++)
                    mma8(acc[mt][nt], af[mt], bf[nt]);
        }
        __syncthreads();
    }

    int c2 = (lid & 3) * 2;
#pragma unroll
    for (int mt = 0; mt < 2; mt++) {
        int row0 = bm + wm * 32 + mt * 16 + g;
#pragma unroll
        for (int nt = 0; nt < 8; nt++) {
            int col = bn + wn * 64 + nt * 8 + c2;
            float b0 = __ldg(bias + col), b1 = __ldg(bias + col + 1);
            float v00 = acc[mt][nt][0] + b0;
            float v01 = acc[mt][nt][1] + b1;
            float v10 = acc[mt][nt][2] + b0;
            float v11 = acc[mt][nt][3] + b1;
            if (EPI == 0) {
                float* C = (float*)Cv;
                const float* r0p = res + (size_t)row0 * Nn + col;
                const float* r1p = res + (size_t)(row0 + 8) * Nn + col;
                *(float2*)(C + (size_t)row0 * Nn + col) =
                    make_float2(v00 + r0p[0], v01 + r0p[1]);
                *(float2*)(C + (size_t)(row0 + 8) * Nn + col) =
                    make_float2(v10 + r1p[0], v11 + r1p[1]);
            } else if (EPI == 1) {
                __nv_bfloat16* C = (__nv_bfloat16*)Cv;
                *(__nv_bfloat162*)(C + (size_t)row0 * Nn + col) =
                    __nv_bfloat162(__float2bfloat16(v00), __float2bfloat16(v01));
                *(__nv_bfloat162*)(C + (size_t)(row0 + 8) * Nn + col) =
                    __nv_bfloat162(__float2bfloat16(v10), __float2bfloat16(v11));
            } else {
                // vT[b][col][l]
                int bz = row0 >> 11, l = row0 & 2047;
                __nv_bfloat16* VT = (__nv_bfloat16*)Cv + (size_t)bz * Cdim * Ldim;
                VT[(size_t)col * Ldim + l]           = __float2bfloat16(v00);
                VT[(size_t)(col + 1) * Ldim + l]     = __float2bfloat16(v01);
                VT[(size_t)col * Ldim + l + 8]       = __float2bfloat16(v10);
                VT[(size_t)(col + 1) * Ldim + l + 8] = __float2bfloat16(v11);
            }
        }
    }
}

// ============================================================
// bf16 GEMM (attention): both operands k-contiguous [rows][k]
//   CTA 128x128, BK=64, smem row stride 72 bf16 (36 words, conflict-free)
//   EPI 0 (QKT): e = exp(acc*SCALE), bf16 out, atomic rowsum partials
//   EPI 1 (PV):  acc / rowsum[row], fp32 out
// ============================================================
template<int EPI>
__global__ void __launch_bounds__(256, 2)
gemm_bf(const __nv_bfloat16* __restrict__ A, const __nv_bfloat16* __restrict__ B,
        float* __restrict__ rowsum, void* __restrict__ Cv,
        int Kn, int ldC, int ldA, int ldB, long sA, long sB, long sC) {
    extern __shared__ float smf[];
    const uint32_t sb = smem_u32(smf);
    int tid = threadIdx.x, wid = tid >> 5, lid = tid & 31;
    int wm = wid & 3, wn = wid >> 2;
    int z = blockIdx.z;
    A += (size_t)z * sA;
    B += (size_t)z * sB;
    int bm = blockIdx.y * 128, bn = blockIdx.x * 128;

    float acc[2][8][4];
#pragma unroll
    for (int mt = 0; mt < 2; mt++)
#pragma unroll
        for (int nt = 0; nt < 8; nt++)
#pragma unroll
            for (int i = 0; i < 4; i++) acc[mt][nt][i] = 0.f;

    const int fr = tid >> 3, fq = tid & 7;          // row, 16B-chunk (8 bf16)
    const __nv_bfloat16* Abase = A + (size_t)bm * ldA;
    const __nv_bfloat16* Bbase = B + (size_t)bn * ldB;

    auto issue = [&](int kc) {
        int k0 = kc << 6;
        uint32_t as = sb + (kc & 1) * 36864;
        uint32_t bs = as + 18432;
#pragma unroll
        for (int i = 0; i < 4; i++) {
            int r = fr + i * 32;
            cpa16(as + r * 144 + fq * 16, Abase + (size_t)r * ldA + k0 + fq * 8);
        }
#pragma unroll
        for (int i = 0; i < 4; i++) {
            int r = fr + i * 32;
            cpa16(bs + r * 144 + fq * 16, Bbase + (size_t)r * ldB + k0 + fq * 8);
        }
        cpa_commit();
    };

    int nch = Kn >> 6;
    issue(0);
    const int g = lid >> 2, c = lid & 3;

    for (int kc = 0; kc < nch; kc++) {
        if (kc + 1 < nch) { issue(kc + 1); cpa_wait<1>(); }
        else cpa_wait<0>();
        __syncthreads();
        const uint32_t* Au = (const uint32_t*)((const char*)smf + (kc & 1) * 36864);
        const uint32_t* Bu = Au + 4608;
#pragma unroll
        for (int s = 0; s < 4; s++) {      // 4 k16 slices
            uint32_t af[2][4];
#pragma unroll
            for (int mt = 0; mt < 2; mt++) {
                int r0 = wm * 32 + mt * 16 + g;
                af[mt][0] = Au[r0 * 36 + 8 * s + c];
                af[mt][1] = Au[(r0 + 8) * 36 + 8 * s + c];
                af[mt][2] = Au[r0 * 36 + 8 * s + c + 4];
                af[mt][3] = Au[(r0 + 8) * 36 + 8 * s + c + 4];
            }
            uint32_t bf[8][2];
#pragma unroll
            for (int nt = 0; nt < 8; nt++) {
                int n0 = wn * 64 + nt * 8 + g;
                bf[nt][0] = Bu[n0 * 36 + 8 * s + c];
                bf[nt][1] = Bu[n0 * 36 + 8 * s + c + 4];
            }
#pragma unroll
            for (int mt = 0; mt < 2; mt++)
#pragma unroll
                for (int nt = 0; nt < 8; nt++)
                    mma16(acc[mt][nt], af[mt], bf[nt]);
        }
        __syncthreads();
    }

    int c2 = (lid & 3) * 2;
    float* rs = rowsum + z * Ldim;
#pragma unroll
    for (int mt = 0; mt < 2; mt++) {
        int row0 = bm + wm * 32 + mt * 16 + g;
        if (EPI == 0) {
            __nv_bfloat16* C = (__nv_bfloat16*)Cv + (size_t)z * sC;
            float s0 = 0.f, s1 = 0.f;
#pragma unroll
            for (int nt = 0; nt < 8; nt++) {
                int col = bn + wn * 64 + nt * 8 + c2;
                float e00 = __expf(acc[mt][nt][0] * SCALE);
                float e01 = __expf(acc[mt][nt][1] * SCALE);
                float e10 = __expf(acc[mt][nt][2] * SCALE);
                float e11 = __expf(acc[mt][nt][3] * SCALE);
                s0 += e00 + e01; s1 += e10 + e11;
                *(__nv_bfloat162*)(C + (size_t)row0 * ldC + col) =
                    __nv_bfloat162(__float2bfloat16(e00), __float2bfloat16(e01));
                *(__nv_bfloat162*)(C + (size_t)(row0 + 8) * ldC + col) =
                    __nv_bfloat162(__float2bfloat16(e10), __float2bfloat16(e11));
            }
            s0 += __shfl_xor_sync(0xffffffffu, s0, 1);
            s0 += __shfl_xor_sync(0xffffffffu, s0, 2);
            s1 += __shfl_xor_sync(0xffffffffu, s1, 1);
            s1 += __shfl_xor_sync(0xffffffffu, s1, 2);
            if ((lid & 3) == 0) {
                atomicAdd(rs + row0, s0);
                atomicAdd(rs + row0 + 8, s1);
            }
        } else {
            float* C = (float*)Cv + (size_t)z * sC;
            float inv0 = __fdividef(1.f, __ldg(rs + row0));
            float inv1 = __fdividef(1.f, __ldg(rs + row0 + 8));
#pragma unroll
            for (int nt = 0; nt < 8; nt++) {
                int col = bn + wn * 64 + nt * 8 + c2;
                *(float2*)(C + (size_t)row0 * ldC + col) =
                    make_float2(acc[mt][nt][0] * inv0, acc[mt][nt][1] * inv0);
                *(float2*)(C + (size_t)(row0 + 8) * ldC + col) =
                    make_float2(acc[mt][nt][2] * inv1, acc[mt][nt][3] * inv1);
            }
        }
    }
}

// ============================================================
// Host launcher
// ============================================================
extern "C" void kernel_launch(void* const* d_in, const int* in_sizes, int n_in,
                              void* d_out, int out_size) {
    const float* x     = (const float*)d_in[0];
    const float* gamma = (const float*)d_in[1];
    const float* beta  = (const float*)d_in[2];
    const float* wq    = (const float*)d_in[3];
    const float* bq    = (const float*)d_in[4];
    const float* wk    = (const float*)d_in[5];
    const float* bk    = (const float*)d_in[6];
    const float* wv    = (const float*)d_in[7];
    const float* bv    = (const float*)d_in[8];
    const float* wp    = (const float*)d_in[9];
    const float* bp    = (const float*)d_in[10];
    float* out = (float*)d_out;

    float *h, *o, *rs;
    __nv_bfloat16 *qb, *kb, *vT, *sbuf;
    cudaGetSymbolAddress((void**)&h, g_h);
    cudaGetSymbolAddress((void**)&o, g_o);
    cudaGetSymbolAddress((void**)&rs, g_rowsum);
    cudaGetSymbolAddress((void**)&qb, g_qb);
    cudaGetSymbolAddress((void**)&kb, g_kb);
    cudaGetSymbolAddress((void**)&vT, g_vT);
    cudaGetSymbolAddress((void**)&sbuf, g_sb);

    static int smem_set = 0;
    if (!smem_set) {
        cudaFuncSetAttribute(gemm_tf32<0>, cudaFuncAttributeMaxDynamicSharedMemorySize, GEMM_SMEM);
        cudaFuncSetAttribute(gemm_tf32<1>, cudaFuncAttributeMaxDynamicSharedMemorySize, GEMM_SMEM);
        cudaFuncSetAttribute(gemm_tf32<2>, cudaFuncAttributeMaxDynamicSharedMemorySize, GEMM_SMEM);
        cudaFuncSetAttribute(gemm_bf<0>, cudaFuncAttributeMaxDynamicSharedMemorySize, GEMM_SMEM);
        cudaFuncSetAttribute(gemm_bf<1>, cudaFuncAttributeMaxDynamicSharedMemorySize, GEMM_SMEM);
        smem_set = 1;
    }

    const long LC = (long)Ldim * Cdim;
    const long LL = (long)Ldim * Ldim;

    // 1) GroupNorm (+ rowsum zero)
    gn_zero<<<1, 64>>>();
    rs_zero<<<Mdim / 256, 256>>>();
    gn_part<<<dim3(16, 64), 256>>>(x);
    gn_apply<<<(Mdim * Cdim / 4) / 256, 256>>>(
        (const float4*)x, (const float4*)gamma, (const float4*)beta);

    // 2) Q, K (bf16 out), V (bf16 transposed out)
    dim3 gProj(Cdim / 128, Mdim / 128, 1);
    gemm_tf32<1><<<gProj, 256, GEMM_SMEM>>>(h, wq, bq, nullptr, qb, Cdim, Cdim, Cdim);
    gemm_tf32<1><<<gProj, 256, GEMM_SMEM>>>(h, wk, bk, nullptr, kb, Cdim, Cdim, Cdim);
    gemm_tf32<2><<<gProj, 256, GEMM_SMEM>>>(h, wv, bv, nullptr, vT, Cdim, Cdim, Cdim);

    // 3) P_unnorm = exp(scale * Q K^T), rowsum partials   (bf16 mma)
    dim3 gS(Ldim / 128, Ldim / 128, Bdim);
    gemm_bf<0><<<gS, 256, GEMM_SMEM>>>(qb, kb, rs, sbuf,
                                       Cdim, Ldim, Cdim, Cdim, LC, LC, LL);

    // 4) O = (P_unnorm @ V) / rowsum   (bf16 mma, vT is [c][l] k-contig)
    dim3 gPV(Cdim / 128, Ldim / 128, Bdim);
    gemm_bf<1><<<gPV, 256, GEMM_SMEM>>>(sbuf, vT, rs, o,
                                        Ldim, Cdim, Ldim, Ldim, LL, LC, LC);

    // 5) out = h + (O @ wp + bp)
    gemm_tf32<0><<<gProj, 256, GEMM_SMEM>>>(o, wp, bp, h, out, Cdim, Cdim, Cdim);
}

// round 11
// speedup vs baseline: 6.5985x; 1.2695x over previous
#include <cuda_runtime.h>
#include <cuda_bf16.h>
#include <math.h>
#include <stdint.h>

#define Bdim 8
#define Ldim 2048
#define Cdim 512
#define Mdim (Bdim*Ldim)          // 16384
#define EPSV 1e-3f
#define SCALE 0.04419417382415922f  // 512^-0.5

// ---- scratch (device globals: allocation-free rule) ----
__device__ float g_h[(size_t)Mdim*Cdim];                   // fp32 residual
__device__ __nv_bfloat16 g_hb[(size_t)Mdim*Cdim];          // bf16 GEMM input
__device__ __nv_bfloat16 g_qb[(size_t)Mdim*Cdim];
__device__ __nv_bfloat16 g_kb[(size_t)Mdim*Cdim];
__device__ __nv_bfloat16 g_vT[(size_t)Mdim*Cdim];          // [b][c][l]
__device__ __nv_bfloat16 g_ob[(size_t)Mdim*Cdim];          // attention out
__device__ __nv_bfloat16 g_sb[(size_t)Bdim*Ldim*Ldim];     // 67 MB P (unnormalized)
__device__ __nv_bfloat16 g_wq[Cdim*Cdim], g_wk[Cdim*Cdim]; // transposed bf16 weights
__device__ __nv_bfloat16 g_wv[Cdim*Cdim], g_wp[Cdim*Cdim];
__device__ float g_rowsum[Mdim];
__device__ float g_sum[64];
__device__ float g_ssum[64];

// ============================================================
// helpers
// ============================================================
__device__ __forceinline__ uint32_t smem_u32(const void* p) {
    uint32_t a;
    asm("{ .reg .u64 t; cvta.to.shared.u64 t, %1; cvt.u32.u64 %0, t; }"
        : "=r"(a) : "l"(p));
    return a;
}
__device__ __forceinline__ void cpa16(uint32_t dst, const void* src) {
    asm volatile("cp.async.cg.shared.global [%0], [%1], 16;"
                 :: "r"(dst), "l"(src) : "memory");
}
__device__ __forceinline__ void cpa_commit() {
    asm volatile("cp.async.commit_group;" ::: "memory");
}
template<int N> __device__ __forceinline__ void cpa_wait() {
    asm volatile("cp.async.wait_group %0;" :: "n"(N) : "memory");
}
__device__ __forceinline__ void mma16(float* d, const uint32_t* a, const uint32_t* b) {
    asm volatile(
        "mma.sync.aligned.m16n8k16.row.col.f32.bf16.bf16.f32 "
        "{%0,%1,%2,%3}, {%4,%5,%6,%7}, {%8,%9}, {%0,%1,%2,%3};"
        : "+f"(d[0]), "+f"(d[1]), "+f"(d[2]), "+f"(d[3])
        : "r"(a[0]), "r"(a[1]), "r"(a[2]), "r"(a[3]), "r"(b[0]), "r"(b[1]));
}

// ============================================================
// GroupNorm + zeros + weight convert/transpose
// ============================================================
__global__ void gn_zero() {
    g_sum[threadIdx.x] = 0.f;
    g_ssum[threadIdx.x] = 0.f;
}
__global__ void rs_zero() {
    g_rowsum[blockIdx.x * 256 + threadIdx.x] = 0.f;
}

__global__ void gn_part(const float* __restrict__ x) {
    int chunk = blockIdx.x;            // 0..15
    int bg = blockIdx.y;               // 0..63
    int b = bg >> 3, g = bg & 7;
    const float* base = x + (size_t)b * Ldim * Cdim + (size_t)chunk * 128 * Cdim + g * 64;
    float s = 0.f, ss = 0.f;
#pragma unroll
    for (int i = 0; i < 8; i++) {
        int idx = threadIdx.x + i * 256;
        int row = idx >> 4, c4 = idx & 15;
        float4 v = *(const float4*)(base + (size_t)row * Cdim + c4 * 4);
        s += v.x + v.y + v.z + v.w;
        ss += v.x*v.x + v.y*v.y + v.z*v.z + v.w*v.w;
    }
#pragma unroll
    for (int o = 16; o > 0; o >>= 1) {
        s  += __shfl_xor_sync(0xffffffffu, s, o);
        ss += __shfl_xor_sync(0xffffffffu, ss, o);
    }
    __shared__ float sh1[8], sh2[8];
    int w = threadIdx.x >> 5;
    if ((threadIdx.x & 31) == 0) { sh1[w] = s; sh2[w] = ss; }
    __syncthreads();
    if (threadIdx.x == 0) {
        float t1 = 0.f, t2 = 0.f;
#pragma unroll
        for (int i = 0; i < 8; i++) { t1 += sh1[i]; t2 += sh2[i]; }
        atomicAdd(&g_sum[bg], t1);
        atomicAdd(&g_ssum[bg], t2);
    }
}

__global__ void gn_apply(const float4* __restrict__ x,
                         const float4* __restrict__ gamma,
                         const float4* __restrict__ beta) {
    int i = blockIdx.x * 256 + threadIdx.x;
    int e = i * 4;
    int ch = e & (Cdim - 1);
    int row = e >> 9;
    int b = row >> 11;
    int g = ch >> 6;
    const float inv = 1.f / (2048.f * 64.f);
    float m = g_sum[b * 8 + g] * inv;
    float r = rsqrtf(g_ssum[b * 8 + g] * inv - m * m + EPSV);
    float4 xv = x[i];
    float4 ga = gamma[ch >> 2];
    float4 be = beta[ch >> 2];
    float4 hv;
    hv.x = (xv.x - m) * r * ga.x + be.x;
    hv.y = (xv.y - m) * r * ga.y + be.y;
    hv.z = (xv.z - m) * r * ga.z + be.z;
    hv.w = (xv.w - m) * r * ga.w + be.w;
    ((float4*)g_h)[i] = hv;
    __nv_bfloat162 p0(__float2bfloat16(hv.x), __float2bfloat16(hv.y));
    __nv_bfloat162 p1(__float2bfloat16(hv.z), __float2bfloat16(hv.w));
    ((__nv_bfloat162*)g_hb)[i * 2]     = p0;
    ((__nv_bfloat162*)g_hb)[i * 2 + 1] = p1;
}

// transpose + bf16 convert: wt[n][k] = w[k][n], 512x512
__global__ void wcvt(const float* __restrict__ w, __nv_bfloat16* __restrict__ wt) {
    __shared__ float t[32][33];
    int bx = blockIdx.x * 32, by = blockIdx.y * 32;
    int tx = threadIdx.x, ty = threadIdx.y;   // 32 x 8
#pragma unroll
    for (int i = 0; i < 32; i += 8)
        t[ty + i][tx] = w[(size_t)(by + ty + i) * Cdim + bx + tx];
    __syncthreads();
#pragma unroll
    for (int i = 0; i < 32; i += 8)
        wt[(size_t)(bx + ty + i) * Cdim + by + tx] = __float2bfloat16(t[tx][ty + i]);
}

// ============================================================
// Unified bf16 GEMM: acc = A[m][k] @ B[n][k]^T   (both k-contig)
//   CTA 128x128, BK=64, smem row stride 72 bf16, 2-stage cp.async
//   EPI 0: +bias -> bf16 out                 (q, k proj)
//   EPI 1: +bias -> bf16 transposed (vT)     (v proj)
//   EPI 2: exp(acc*SCALE) -> bf16, rowsum    (QKT)
//   EPI 3: acc/rowsum -> bf16 out            (PV)
//   EPI 4: +bias +res(fp32) -> fp32 out      (out-proj)
// ============================================================
#define GEMM_SMEM 73728

template<int EPI>
__global__ void __launch_bounds__(256, 2)
gemm_bf(const __nv_bfloat16* __restrict__ A, const __nv_bfloat16* __restrict__ B,
        const float* __restrict__ bias, const float* __restrict__ res,
        float* __restrict__ rowsum, void* __restrict__ Cv,
        int Kn, int ldA, int ldB, int ldC, long sA, long sB, long sC) {
    extern __shared__ float smf[];
    const uint32_t sb = smem_u32(smf);
    int tid = threadIdx.x, wid = tid >> 5, lid = tid & 31;
    int wm = wid & 3, wn = wid >> 2;
    int z = blockIdx.z;
    A += (size_t)z * sA;
    B += (size_t)z * sB;
    int bm = blockIdx.y * 128, bn = blockIdx.x * 128;

    float acc[2][8][4];
#pragma unroll
    for (int mt = 0; mt < 2; mt++)
#pragma unroll
        for (int nt = 0; nt < 8; nt++)
#pragma unroll
            for (int i = 0; i < 4; i++) acc[mt][nt][i] = 0.f;

    const int fr = tid >> 3, fq = tid & 7;
    const __nv_bfloat16* Abase = A + (size_t)bm * ldA;
    const __nv_bfloat16* Bbase = B + (size_t)bn * ldB;

    auto issue = [&](int kc) {
        int k0 = kc << 6;
        uint32_t as = sb + (kc & 1) * 36864;
        uint32_t bs = as + 18432;
#pragma unroll
        for (int i = 0; i < 4; i++) {
            int r = fr + i * 32;
            cpa16(as + r * 144 + fq * 16, Abase + (size_t)r * ldA + k0 + fq * 8);
        }
#pragma unroll
        for (int i = 0; i < 4; i++) {
            int r = fr + i * 32;
            cpa16(bs + r * 144 + fq * 16, Bbase + (size_t)r * ldB + k0 + fq * 8);
        }
        cpa_commit();
    };

    int nch = Kn >> 6;
    issue(0);
    const int g = lid >> 2, c = lid & 3;

    for (int kc = 0; kc < nch; kc++) {
        if (kc + 1 < nch) { issue(kc + 1); cpa_wait<1>(); }
        else cpa_wait<0>();
        __syncthreads();
        const uint32_t* Au = (const uint32_t*)((const char*)smf + (kc & 1) * 36864);
        const uint32_t* Bu = Au + 4608;
#pragma unroll
        for (int s = 0; s < 4; s++) {
            uint32_t af[2][4];
#pragma unroll
            for (int mt = 0; mt < 2; mt++) {
                int r0 = wm * 32 + mt * 16 + g;
                af[mt][0] = Au[r0 * 36 + 8 * s + c];
                af[mt][1] = Au[(r0 + 8) * 36 + 8 * s + c];
                af[mt][2] = Au[r0 * 36 + 8 * s + c + 4];
                af[mt][3] = Au[(r0 + 8) * 36 + 8 * s + c + 4];
            }
            uint32_t bf[8][2];
#pragma unroll
            for (int nt = 0; nt < 8; nt++) {
                int n0 = wn * 64 + nt * 8 + g;
                bf[nt][0] = Bu[n0 * 36 + 8 * s + c];
                bf[nt][1] = Bu[n0 * 36 + 8 * s + c + 4];
            }
#pragma unroll
            for (int mt = 0; mt < 2; mt++)
#pragma unroll
                for (int nt = 0; nt < 8; nt++)
                    mma16(acc[mt][nt], af[mt], bf[nt]);
        }
        __syncthreads();
    }

    int c2 = (lid & 3) * 2;
    float* rs = rowsum ? rowsum + z * Ldim : nullptr;
#pragma unroll
    for (int mt = 0; mt < 2; mt++) {
        int row0 = bm + wm * 32 + mt * 16 + g;
        if (EPI == 0) {
            __nv_bfloat16* C = (__nv_bfloat16*)Cv;
#pragma unroll
            for (int nt = 0; nt < 8; nt++) {
                int col = bn + wn * 64 + nt * 8 + c2;
                float b0 = __ldg(bias + col), b1 = __ldg(bias + col + 1);
                *(__nv_bfloat162*)(C + (size_t)row0 * ldC + col) =
                    __nv_bfloat162(__float2bfloat16(acc[mt][nt][0] + b0),
                                   __float2bfloat16(acc[mt][nt][1] + b1));
                *(__nv_bfloat162*)(C + (size_t)(row0 + 8) * ldC + col) =
                    __nv_bfloat162(__float2bfloat16(acc[mt][nt][2] + b0),
                                   __float2bfloat16(acc[mt][nt][3] + b1));
            }
        } else if (EPI == 1) {
            int bz = row0 >> 11, l = row0 & 2047;
            __nv_bfloat16* VT = (__nv_bfloat16*)Cv + (size_t)bz * Cdim * Ldim;
#pragma unroll
            for (int nt = 0; nt < 8; nt++) {
                int col = bn + wn * 64 + nt * 8 + c2;
                float b0 = __ldg(bias + col), b1 = __ldg(bias + col + 1);
                VT[(size_t)col * Ldim + l]           = __float2bfloat16(acc[mt][nt][0] + b0);
                VT[(size_t)(col + 1) * Ldim + l]     = __float2bfloat16(acc[mt][nt][1] + b1);
                VT[(size_t)col * Ldim + l + 8]       = __float2bfloat16(acc[mt][nt][2] + b0);
                VT[(size_t)(col + 1) * Ldim + l + 8] = __float2bfloat16(acc[mt][nt][3] + b1);
            }
        } else if (EPI == 2) {
            __nv_bfloat16* C = (__nv_bfloat16*)Cv + (size_t)z * sC;
            float s0 = 0.f, s1 = 0.f;
#pragma unroll
            for (int nt = 0; nt < 8; nt++) {
                int col = bn + wn * 64 + nt * 8 + c2;
                float e00 = __expf(acc[mt][nt][0] * SCALE);
                float e01 = __expf(acc[mt][nt][1] * SCALE);
                float e10 = __expf(acc[mt][nt][2] * SCALE);
                float e11 = __expf(acc[mt][nt][3] * SCALE);
                s0 += e00 + e01; s1 += e10 + e11;
                *(__nv_bfloat162*)(C + (size_t)row0 * ldC + col) =
                    __nv_bfloat162(__float2bfloat16(e00), __float2bfloat16(e01));
                *(__nv_bfloat162*)(C + (size_t)(row0 + 8) * ldC + col) =
                    __nv_bfloat162(__float2bfloat16(e10), __float2bfloat16(e11));
            }
            s0 += __shfl_xor_sync(0xffffffffu, s0, 1);
            s0 += __shfl_xor_sync(0xffffffffu, s0, 2);
            s1 += __shfl_xor_sync(0xffffffffu, s1, 1);
            s1 += __shfl_xor_sync(0xffffffffu, s1, 2);
            if ((lid & 3) == 0) {
                atomicAdd(rs + row0, s0);
                atomicAdd(rs + row0 + 8, s1);
            }
        } else if (EPI == 3) {
            __nv_bfloat16* C = (__nv_bfloat16*)Cv + (size_t)z * sC;
            float inv0 = __fdividef(1.f, __ldg(rs + row0));
            float inv1 = __fdividef(1.f, __ldg(rs + row0 + 8));
#pragma unroll
            for (int nt = 0; nt < 8; nt++) {
                int col = bn + wn * 64 + nt * 8 + c2;
                *(__nv_bfloat162*)(C + (size_t)row0 * ldC + col) =
                    __nv_bfloat162(__float2bfloat16(acc[mt][nt][0] * inv0),
                                   __float2bfloat16(acc[mt][nt][1] * inv0));
                *(__nv_bfloat162*)(C + (size_t)(row0 + 8) * ldC + col) =
                    __nv_bfloat162(__float2bfloat16(acc[mt][nt][2] * inv1),
                                   __float2bfloat16(acc[mt][nt][3] * inv1));
            }
        } else {
            float* C = (float*)Cv;
#pragma unroll
            for (int nt = 0; nt < 8; nt++) {
                int col = bn + wn * 64 + nt * 8 + c2;
                float b0 = __ldg(bias + col), b1 = __ldg(bias + col + 1);
                const float* r0p = res + (size_t)row0 * ldC + col;
                const float* r1p = res + (size_t)(row0 + 8) * ldC + col;
                *(float2*)(C + (size_t)row0 * ldC + col) =
                    make_float2(acc[mt][nt][0] + b0 + r0p[0],
                                acc[mt][nt][1] + b1 + r0p[1]);
                *(float2*)(C + (size_t)(row0 + 8) * ldC + col) =
                    make_float2(acc[mt][nt][2] + b0 + r1p[0],
                                acc[mt][nt][3] + b1 + r1p[1]);
            }
        }
    }
}

// ============================================================
// Host launcher
// ============================================================
extern "C" void kernel_launch(void* const* d_in, const int* in_sizes, int n_in,
                              void* d_out, int out_size) {
    const float* x     = (const float*)d_in[0];
    const float* gamma = (const float*)d_in[1];
    const float* beta  = (const float*)d_in[2];
    const float* wq    = (const float*)d_in[3];
    const float* bq    = (const float*)d_in[4];
    const float* wk    = (const float*)d_in[5];
    const float* bk    = (const float*)d_in[6];
    const float* wv    = (const float*)d_in[7];
    const float* bv    = (const float*)d_in[8];
    const float* wp    = (const float*)d_in[9];
    const float* bp    = (const float*)d_in[10];
    float* out = (float*)d_out;

    float *h, *rs;
    __nv_bfloat16 *hb, *qb, *kb, *vT, *ob, *sbuf, *wqT, *wkT, *wvT, *wpT;
    cudaGetSymbolAddress((void**)&h,  g_h);
    cudaGetSymbolAddress((void**)&hb, g_hb);
    cudaGetSymbolAddress((void**)&rs, g_rowsum);
    cudaGetSymbolAddress((void**)&qb, g_qb);
    cudaGetSymbolAddress((void**)&kb, g_kb);
    cudaGetSymbolAddress((void**)&vT, g_vT);
    cudaGetSymbolAddress((void**)&ob, g_ob);
    cudaGetSymbolAddress((void**)&sbuf, g_sb);
    cudaGetSymbolAddress((void**)&wqT, g_wq);
    cudaGetSymbolAddress((void**)&wkT, g_wk);
    cudaGetSymbolAddress((void**)&wvT, g_wv);
    cudaGetSymbolAddress((void**)&wpT, g_wp);

    static int smem_set = 0;
    if (!smem_set) {
        cudaFuncSetAttribute(gemm_bf<0>, cudaFuncAttributeMaxDynamicSharedMemorySize, GEMM_SMEM);
        cudaFuncSetAttribute(gemm_bf<1>, cudaFuncAttributeMaxDynamicSharedMemorySize, GEMM_SMEM);
        cudaFuncSetAttribute(gemm_bf<2>, cudaFuncAttributeMaxDynamicSharedMemorySize, GEMM_SMEM);
        cudaFuncSetAttribute(gemm_bf<3>, cudaFuncAttributeMaxDynamicSharedMemorySize, GEMM_SMEM);
        cudaFuncSetAttribute(gemm_bf<4>, cudaFuncAttributeMaxDynamicSharedMemorySize, GEMM_SMEM);
        smem_set = 1;
    }

    const long LC = (long)Ldim * Cdim;
    const long LL = (long)Ldim * Ldim;

    // 1) GroupNorm + zeros + weight transposes
    gn_zero<<<1, 64>>>();
    rs_zero<<<Mdim / 256, 256>>>();
    gn_part<<<dim3(16, 64), 256>>>(x);
    gn_apply<<<(Mdim * Cdim / 4) / 256, 256>>>(
        (const float4*)x, (const float4*)gamma, (const float4*)beta);
    dim3 wg(16, 16), wb(32, 8);
    wcvt<<<wg, wb>>>(wq, wqT);
    wcvt<<<wg, wb>>>(wk, wkT);
    wcvt<<<wg, wb>>>(wv, wvT);
    wcvt<<<wg, wb>>>(wp, wpT);

    // 2) Q, K, V projections (all bf16)
    dim3 gProj(Cdim / 128, Mdim / 128, 1);
    gemm_bf<0><<<gProj, 256, GEMM_SMEM>>>(hb, wqT, bq, nullptr, nullptr, qb,
                                          Cdim, Cdim, Cdim, Cdim, 0, 0, 0);
    gemm_bf<0><<<gProj, 256, GEMM_SMEM>>>(hb, wkT, bk, nullptr, nullptr, kb,
                                          Cdim, Cdim, Cdim, Cdim, 0, 0, 0);
    gemm_bf<1><<<gProj, 256, GEMM_SMEM>>>(hb, wvT, bv, nullptr, nullptr, vT,
                                          Cdim, Cdim, Cdim, Cdim, 0, 0, 0);

    // 3) P_unnorm = exp(scale * Q K^T), rowsum partials
    dim3 gS(Ldim / 128, Ldim / 128, Bdim);
    gemm_bf<2><<<gS, 256, GEMM_SMEM>>>(qb, kb, nullptr, nullptr, rs, sbuf,
                                       Cdim, Cdim, Cdim, Ldim, LC, LC, LL);

    // 4) O = (P_unnorm @ V) / rowsum  -> bf16
    dim3 gPV(Cdim / 128, Ldim / 128, Bdim);
    gemm_bf<3><<<gPV, 256, GEMM_SMEM>>>(sbuf, vT, nullptr, nullptr, rs, ob,
                                        Ldim, Ldim, Ldim, Cdim, LL, LC, LC);

    // 5) out = h + (O @ wp + bp)
    gemm_bf<4><<<gProj, 256, GEMM_SMEM>>>(ob, wpT, bp, h, nullptr, out,
                                          Cdim, Cdim, Cdim, Cdim, 0, 0, 0);
}

// round 12
// speedup vs baseline: 7.0360x; 1.0663x over previous
#include <cuda_runtime.h>
#include <cuda_bf16.h>
#include <math.h>
#include <stdint.h>

#define Bdim 8
#define Ldim 2048
#define Cdim 512
#define Mdim (Bdim*Ldim)          // 16384
#define EPSV 1e-3f
#define SCALE 0.04419417382415922f  // 512^-0.5

// ---- scratch (device globals: allocation-free rule) ----
__device__ float g_h[(size_t)Mdim*Cdim];                   // fp32 residual
__device__ __nv_bfloat16 g_hb[(size_t)Mdim*Cdim];          // bf16 GEMM input
__device__ __nv_bfloat16 g_qb[(size_t)Mdim*Cdim];
__device__ __nv_bfloat16 g_kb[(size_t)Mdim*Cdim];
__device__ __nv_bfloat16 g_vT[(size_t)Mdim*Cdim];          // [b][c][l]
__device__ __nv_bfloat16 g_ob[(size_t)Mdim*Cdim];          // attention out
__device__ __nv_bfloat16 g_sb[(size_t)Bdim*Ldim*Ldim];     // 67 MB P (unnormalized)
__device__ __nv_bfloat16 g_wq[Cdim*Cdim], g_wk[Cdim*Cdim]; // transposed bf16 weights
__device__ __nv_bfloat16 g_wv[Cdim*Cdim], g_wp[Cdim*Cdim];
__device__ float g_rowsum[Mdim];
__device__ float g_sum[64];
__device__ float g_ssum[64];

// ============================================================
// helpers
// ============================================================
__device__ __forceinline__ uint32_t smem_u32(const void* p) {
    uint32_t a;
    asm("{ .reg .u64 t; cvta.to.shared.u64 t, %1; cvt.u32.u64 %0, t; }"
        : "=r"(a) : "l"(p));
    return a;
}
__device__ __forceinline__ void cpa16(uint32_t dst, const void* src) {
    asm volatile("cp.async.cg.shared.global [%0], [%1], 16;"
                 :: "r"(dst), "l"(src) : "memory");
}
__device__ __forceinline__ void cpa_commit() {
    asm volatile("cp.async.commit_group;" ::: "memory");
}
template<int N> __device__ __forceinline__ void cpa_wait() {
    asm volatile("cp.async.wait_group %0;" :: "n"(N) : "memory");
}
__device__ __forceinline__ void mma16(float* d, const uint32_t* a, const uint32_t* b) {
    asm volatile(
        "mma.sync.aligned.m16n8k16.row.col.f32.bf16.bf16.f32 "
        "{%0,%1,%2,%3}, {%4,%5,%6,%7}, {%8,%9}, {%0,%1,%2,%3};"
        : "+f"(d[0]), "+f"(d[1]), "+f"(d[2]), "+f"(d[3])
        : "r"(a[0]), "r"(a[1]), "r"(a[2]), "r"(a[3]), "r"(b[0]), "r"(b[1]));
}
__device__ __forceinline__ void ldsm4(uint32_t* r, uint32_t addr) {
    asm volatile("ldmatrix.sync.aligned.m8n8.x4.shared.b16 {%0,%1,%2,%3}, [%4];"
        : "=r"(r[0]), "=r"(r[1]), "=r"(r[2]), "=r"(r[3]) : "r"(addr));
}

// ============================================================
// GroupNorm + zeros + weight convert/transpose
// ============================================================
__global__ void zeros_k() {       // grid 64 x 256: rowsum + gn partials
    int i = blockIdx.x * 256 + threadIdx.x;
    g_rowsum[i] = 0.f;
    if (i < 64) { g_sum[i] = 0.f; g_ssum[i] = 0.f; }
}

__global__ void gn_part(const float* __restrict__ x) {
    int chunk = blockIdx.x;            // 0..15
    int bg = blockIdx.y;               // 0..63
    int b = bg >> 3, g = bg & 7;
    const float* base = x + (size_t)b * Ldim * Cdim + (size_t)chunk * 128 * Cdim + g * 64;
    float s = 0.f, ss = 0.f;
#pragma unroll
    for (int i = 0; i < 8; i++) {
        int idx = threadIdx.x + i * 256;
        int row = idx >> 4, c4 = idx & 15;
        float4 v = *(const float4*)(base + (size_t)row * Cdim + c4 * 4);
        s += v.x + v.y + v.z + v.w;
        ss += v.x*v.x + v.y*v.y + v.z*v.z + v.w*v.w;
    }
#pragma unroll
    for (int o = 16; o > 0; o >>= 1) {
        s  += __shfl_xor_sync(0xffffffffu, s, o);
        ss += __shfl_xor_sync(0xffffffffu, ss, o);
    }
    __shared__ float sh1[8], sh2[8];
    int w = threadIdx.x >> 5;
    if ((threadIdx.x & 31) == 0) { sh1[w] = s; sh2[w] = ss; }
    __syncthreads();
    if (threadIdx.x == 0) {
        float t1 = 0.f, t2 = 0.f;
#pragma unroll
        for (int i = 0; i < 8; i++) { t1 += sh1[i]; t2 += sh2[i]; }
        atomicAdd(&g_sum[bg], t1);
        atomicAdd(&g_ssum[bg], t2);
    }
}

__global__ void gn_apply(const float4* __restrict__ x,
                         const float4* __restrict__ gamma,
                         const float4* __restrict__ beta) {
    int i = blockIdx.x * 256 + threadIdx.x;
    int e = i * 4;
    int ch = e & (Cdim - 1);
    int row = e >> 9;
    int b = row >> 11;
    int g = ch >> 6;
    const float inv = 1.f / (2048.f * 64.f);
    float m = g_sum[b * 8 + g] * inv;
    float r = rsqrtf(g_ssum[b * 8 + g] * inv - m * m + EPSV);
    float4 xv = x[i];
    float4 ga = gamma[ch >> 2];
    float4 be = beta[ch >> 2];
    float4 hv;
    hv.x = (xv.x - m) * r * ga.x + be.x;
    hv.y = (xv.y - m) * r * ga.y + be.y;
    hv.z = (xv.z - m) * r * ga.z + be.z;
    hv.w = (xv.w - m) * r * ga.w + be.w;
    ((float4*)g_h)[i] = hv;
    __nv_bfloat162 p0(__float2bfloat16(hv.x), __float2bfloat16(hv.y));
    __nv_bfloat162 p1(__float2bfloat16(hv.z), __float2bfloat16(hv.w));
    ((__nv_bfloat162*)g_hb)[i * 2]     = p0;
    ((__nv_bfloat162*)g_hb)[i * 2 + 1] = p1;
}

// transpose + bf16 convert: wt[n][k] = w[k][n], 512x512
__global__ void wcvt(const float* __restrict__ w, __nv_bfloat16* __restrict__ wt) {
    __shared__ float t[32][33];
    int bx = blockIdx.x * 32, by = blockIdx.y * 32;
    int tx = threadIdx.x, ty = threadIdx.y;   // 32 x 8
#pragma unroll
    for (int i = 0; i < 32; i += 8)
        t[ty + i][tx] = w[(size_t)(by + ty + i) * Cdim + bx + tx];
    __syncthreads();
#pragma unroll
    for (int i = 0; i < 32; i += 8)
        wt[(size_t)(bx + ty + i) * Cdim + by + tx] = __float2bfloat16(t[tx][ty + i]);
}

// ============================================================
// Unified bf16 GEMM: acc = A[m][k] @ B[n][k]^T   (both k-contig)
//   CTA 128x128, BK=64, smem row stride 72 bf16 (144 B), 2-stage cp.async
//   fragment feed via ldmatrix.x4 (conflict-free at 144B stride)
//   EPI 0: +bias -> bf16 out                 (q, k proj)
//   EPI 1: +bias -> bf16 transposed (vT)     (v proj)
//   EPI 2: exp(acc*SCALE) -> bf16, rowsum    (QKT)
//   EPI 3: acc/rowsum -> bf16 out            (PV)
//   EPI 4: +bias +res(fp32) -> fp32 out      (out-proj)
// ============================================================
#define GEMM_SMEM 73728

template<int EPI>
__global__ void __launch_bounds__(256, 2)
gemm_bf(const __nv_bfloat16* __restrict__ A, const __nv_bfloat16* __restrict__ B,
        const float* __restrict__ bias, const float* __restrict__ res,
        float* __restrict__ rowsum, void* __restrict__ Cv,
        int Kn, int ldA, int ldB, int ldC, long sA, long sB, long sC) {
    extern __shared__ float smf[];
    const uint32_t sb = smem_u32(smf);
    int tid = threadIdx.x, wid = tid >> 5, lid = tid & 31;
    int wm = wid & 3, wn = wid >> 2;
    int z = blockIdx.z;
    A += (size_t)z * sA;
    B += (size_t)z * sB;
    int bm = blockIdx.y * 128, bn = blockIdx.x * 128;

    float acc[2][8][4];
#pragma unroll
    for (int mt = 0; mt < 2; mt++)
#pragma unroll
        for (int nt = 0; nt < 8; nt++)
#pragma unroll
            for (int i = 0; i < 4; i++) acc[mt][nt][i] = 0.f;

    const int fr = tid >> 3, fq = tid & 7;
    const __nv_bfloat16* Abase = A + (size_t)bm * ldA;
    const __nv_bfloat16* Bbase = B + (size_t)bn * ldB;

    auto issue = [&](int kc) {
        int k0 = kc << 6;
        uint32_t as = sb + (kc & 1) * 36864;
        uint32_t bs = as + 18432;
#pragma unroll
        for (int i = 0; i < 4; i++) {
            int r = fr + i * 32;
            cpa16(as + r * 144 + fq * 16, Abase + (size_t)r * ldA + k0 + fq * 8);
        }
#pragma unroll
        for (int i = 0; i < 4; i++) {
            int r = fr + i * 32;
            cpa16(bs + r * 144 + fq * 16, Bbase + (size_t)r * ldB + k0 + fq * 8);
        }
        cpa_commit();
    };

    int nch = Kn >> 6;
    issue(0);

    // ldmatrix base addresses (per stage, add stage offset inside loop)
    // A: lanes 0-7 rows 0-7 k0 | 8-15 rows 8-15 k0 | 16-23 rows 0-7 k8 | 24-31 rows 8-15 k8
    uint32_t aoff0 = (uint32_t)((wm * 32 + (lid & 15)) * 144 + (lid >> 4) * 16);
    uint32_t aoff1 = aoff0 + 16 * 144;
    // B: per np (pair of n8 tiles): m0 rows n0..7 k0 | m1 same k8 | m2 rows n8..15 k0 | m3 k8
    uint32_t boff = (uint32_t)((wn * 64 + (lid & 7) + ((lid >> 4) & 1) * 8) * 144
                               + ((lid >> 3) & 1) * 16);

    for (int kc = 0; kc < nch; kc++) {
        if (kc + 1 < nch) { issue(kc + 1); cpa_wait<1>(); }
        else cpa_wait<0>();
        __syncthreads();
        uint32_t as = sb + (kc & 1) * 36864;
        uint32_t bs = as + 18432;
#pragma unroll
        for (int s = 0; s < 4; s++) {
            uint32_t af[2][4];
            ldsm4(af[0], as + aoff0 + s * 32);
            ldsm4(af[1], as + aoff1 + s * 32);
            uint32_t bf[4][4];
#pragma unroll
            for (int np = 0; np < 4; np++)
                ldsm4(bf[np], bs + boff + np * 16 * 144 + s * 32);
#pragma unroll
            for (int mt = 0; mt < 2; mt++)
#pragma unroll
                for (int nt = 0; nt < 8; nt++)
                    mma16(acc[mt][nt], af[mt], &bf[nt >> 1][(nt & 1) * 2]);
        }
        __syncthreads();
    }

    int c2 = (lid & 3) * 2;
    const int g = lid >> 2;
    float* rs = rowsum ? rowsum + z * Ldim : nullptr;
#pragma unroll
    for (int mt = 0; mt < 2; mt++) {
        int row0 = bm + wm * 32 + mt * 16 + g;
        if (EPI == 0) {
            __nv_bfloat16* C = (__nv_bfloat16*)Cv;
#pragma unroll
            for (int nt = 0; nt < 8; nt++) {
                int col = bn + wn * 64 + nt * 8 + c2;
                float b0 = __ldg(bias + col), b1 = __ldg(bias + col + 1);
                *(__nv_bfloat162*)(C + (size_t)row0 * ldC + col) =
                    __nv_bfloat162(__float2bfloat16(acc[mt][nt][0] + b0),
                                   __float2bfloat16(acc[mt][nt][1] + b1));
                *(__nv_bfloat162*)(C + (size_t)(row0 + 8) * ldC + col) =
                    __nv_bfloat162(__float2bfloat16(acc[mt][nt][2] + b0),
                                   __float2bfloat16(acc[mt][nt][3] + b1));
            }
        } else if (EPI == 1) {
            int bz = row0 >> 11, l = row0 & 2047;
            __nv_bfloat16* VT = (__nv_bfloat16*)Cv + (size_t)bz * Cdim * Ldim;
#pragma unroll
            for (int nt = 0; nt < 8; nt++) {
                int col = bn + wn * 64 + nt * 8 + c2;
                float b0 = __ldg(bias + col), b1 = __ldg(bias + col + 1);
                VT[(size_t)col * Ldim + l]           = __float2bfloat16(acc[mt][nt][0] + b0);
                VT[(size_t)(col + 1) * Ldim + l]     = __float2bfloat16(acc[mt][nt][1] + b1);
                VT[(size_t)col * Ldim + l + 8]       = __float2bfloat16(acc[mt][nt][2] + b0);
                VT[(size_t)(col + 1) * Ldim + l + 8] = __float2bfloat16(acc[mt][nt][3] + b1);
            }
        } else if (EPI == 2) {
            __nv_bfloat16* C = (__nv_bfloat16*)Cv + (size_t)z * sC;
            float s0 = 0.f, s1 = 0.f;
#pragma unroll
            for (int nt = 0; nt < 8; nt++) {
                int col = bn + wn * 64 + nt * 8 + c2;
                float e00 = __expf(acc[mt][nt][0] * SCALE);
                float e01 = __expf(acc[mt][nt][1] * SCALE);
                float e10 = __expf(acc[mt][nt][2] * SCALE);
                float e11 = __expf(acc[mt][nt][3] * SCALE);
                s0 += e00 + e01; s1 += e10 + e11;
                *(__nv_bfloat162*)(C + (size_t)row0 * ldC + col) =
                    __nv_bfloat162(__float2bfloat16(e00), __float2bfloat16(e01));
                *(__nv_bfloat162*)(C + (size_t)(row0 + 8) * ldC + col) =
                    __nv_bfloat162(__float2bfloat16(e10), __float2bfloat16(e11));
            }
            s0 += __shfl_xor_sync(0xffffffffu, s0, 1);
            s0 += __shfl_xor_sync(0xffffffffu, s0, 2);
            s1 += __shfl_xor_sync(0xffffffffu, s1, 1);
            s1 += __shfl_xor_sync(0xffffffffu, s1, 2);
            if ((lid & 3) == 0) {
                atomicAdd(rs + row0, s0);
                atomicAdd(rs + row0 + 8, s1);
            }
        } else if (EPI == 3) {
            __nv_bfloat16* C = (__nv_bfloat16*)Cv + (size_t)z * sC;
            float inv0 = __fdividef(1.f, __ldg(rs + row0));
            float inv1 = __fdividef(1.f, __ldg(rs + row0 + 8));
#pragma unroll
            for (int nt = 0; nt < 8; nt++) {
                int col = bn + wn * 64 + nt * 8 + c2;
                *(__nv_bfloat162*)(C + (size_t)row0 * ldC + col) =
                    __nv_bfloat162(__float2bfloat16(acc[mt][nt][0] * inv0),
                                   __float2bfloat16(acc[mt][nt][1] * inv0));
                *(__nv_bfloat162*)(C + (size_t)(row0 + 8) * ldC + col) =
                    __nv_bfloat162(__float2bfloat16(acc[mt][nt][2] * inv1),
                                   __float2bfloat16(acc[mt][nt][3] * inv1));
            }
        } else {
            float* C = (float*)Cv;
#pragma unroll
            for (int nt = 0; nt < 8; nt++) {
                int col = bn + wn * 64 + nt * 8 + c2;
                float b0 = __ldg(bias + col), b1 = __ldg(bias + col + 1);
                const float* r0p = res + (size_t)row0 * ldC + col;
                const float* r1p = res + (size_t)(row0 + 8) * ldC + col;
                *(float2*)(C + (size_t)row0 * ldC + col) =
                    make_float2(acc[mt][nt][0] + b0 + r0p[0],
                                acc[mt][nt][1] + b1 + r0p[1]);
                *(float2*)(C + (size_t)(row0 + 8) * ldC + col) =
                    make_float2(acc[mt][nt][2] + b0 + r1p[0],
                                acc[mt][nt][3] + b1 + r1p[1]);
            }
        }
    }
}

// ============================================================
// Host launcher
// ============================================================
extern "C" void kernel_launch(void* const* d_in, const int* in_sizes, int n_in,
                              void* d_out, int out_size) {
    const float* x     = (const float*)d_in[0];
    const float* gamma = (const float*)d_in[1];
    const float* beta  = (const float*)d_in[2];
    const float* wq    = (const float*)d_in[3];
    const float* bq    = (const float*)d_in[4];
    const float* wk    = (const float*)d_in[5];
    const float* bk    = (const float*)d_in[6];
    const float* wv    = (const float*)d_in[7];
    const float* bv    = (const float*)d_in[8];
    const float* wp    = (const float*)d_in[9];
    const float* bp    = (const float*)d_in[10];
    float* out = (float*)d_out;

    float *h, *rs;
    __nv_bfloat16 *hb, *qb, *kb, *vT, *ob, *sbuf, *wqT, *wkT, *wvT, *wpT;
    cudaGetSymbolAddress((void**)&h,  g_h);
    cudaGetSymbolAddress((void**)&hb, g_hb);
    cudaGetSymbolAddress((void**)&rs, g_rowsum);
    cudaGetSymbolAddress((void**)&qb, g_qb);
    cudaGetSymbolAddress((void**)&kb, g_kb);
    cudaGetSymbolAddress((void**)&vT, g_vT);
    cudaGetSymbolAddress((void**)&ob, g_ob);
    cudaGetSymbolAddress((void**)&sbuf, g_sb);
    cudaGetSymbolAddress((void**)&wqT, g_wq);
    cudaGetSymbolAddress((void**)&wkT, g_wk);
    cudaGetSymbolAddress((void**)&wvT, g_wv);
    cudaGetSymbolAddress((void**)&wpT, g_wp);

    static int smem_set = 0;
    if (!smem_set) {
        cudaFuncSetAttribute(gemm_bf<0>, cudaFuncAttributeMaxDynamicSharedMemorySize, GEMM_SMEM);
        cudaFuncSetAttribute(gemm_bf<1>, cudaFuncAttributeMaxDynamicSharedMemorySize, GEMM_SMEM);
        cudaFuncSetAttribute(gemm_bf<2>, cudaFuncAttributeMaxDynamicSharedMemorySize, GEMM_SMEM);
        cudaFuncSetAttribute(gemm_bf<3>, cudaFuncAttributeMaxDynamicSharedMemorySize, GEMM_SMEM);
        cudaFuncSetAttribute(gemm_bf<4>, cudaFuncAttributeMaxDynamicSharedMemorySize, GEMM_SMEM);
        smem_set = 1;
    }

    const long LC = (long)Ldim * Cdim;
    const long LL = (long)Ldim * Ldim;

    // 1) GroupNorm + zeros + weight transposes
    zeros_k<<<64, 256>>>();
    gn_part<<<dim3(16, 64), 256>>>(x);
    gn_apply<<<(Mdim * Cdim / 4) / 256, 256>>>(
        (const float4*)x, (const float4*)gamma, (const float4*)beta);
    dim3 wg(16, 16), wb(32, 8);
    wcvt<<<wg, wb>>>(wq, wqT);
    wcvt<<<wg, wb>>>(wk, wkT);
    wcvt<<<wg, wb>>>(wv, wvT);
    wcvt<<<wg, wb>>>(wp, wpT);

    // 2) Q, K, V projections (all bf16)
    dim3 gProj(Cdim / 128, Mdim / 128, 1);
    gemm_bf<0><<<gProj, 256, GEMM_SMEM>>>(hb, wqT, bq, nullptr, nullptr, qb,
                                          Cdim, Cdim, Cdim, Cdim, 0, 0, 0);
    gemm_bf<0><<<gProj, 256, GEMM_SMEM>>>(hb, wkT, bk, nullptr, nullptr, kb,
                                          Cdim, Cdim, Cdim, Cdim, 0, 0, 0);
    gemm_bf<1><<<gProj, 256, GEMM_SMEM>>>(hb, wvT, bv, nullptr, nullptr, vT,
                                          Cdim, Cdim, Cdim, Cdim, 0, 0, 0);

    // 3) P_unnorm = exp(scale * Q K^T), rowsum partials
    dim3 gS(Ldim / 128, Ldim / 128, Bdim);
    gemm_bf<2><<<gS, 256, GEMM_SMEM>>>(qb, kb, nullptr, nullptr, rs, sbuf,
                                       Cdim, Cdim, Cdim, Ldim, LC, LC, LL);

    // 4) O = (P_unnorm @ V) / rowsum  -> bf16
    dim3 gPV(Cdim / 128, Ldim / 128, Bdim);
    gemm_bf<3><<<gPV, 256, GEMM_SMEM>>>(sbuf, vT, nullptr, nullptr, rs, ob,
                                        Ldim, Ldim, Ldim, Cdim, LL, LC, LC);

    // 5) out = h + (O @ wp + bp)
    gemm_bf<4><<<gProj, 256, GEMM_SMEM>>>(ob, wpT, bp, h, nullptr, out,
                                          Cdim, Cdim, Cdim, Cdim, 0, 0, 0);
}

// round 14
// speedup vs baseline: 7.3834x; 1.0494x over previous
#include <cuda_runtime.h>
#include <cuda_bf16.h>
#include <math.h>
#include <stdint.h>

#define Bdim 8
#define Ldim 2048
#define Cdim 512
#define Mdim (Bdim*Ldim)          // 16384
#define EPSV 1e-3f
#define SCALE 0.04419417382415922f  // 512^-0.5

// ---- scratch (device globals: allocation-free rule) ----
__device__ float g_h[(size_t)Mdim*Cdim];                   // fp32 residual
__device__ __nv_bfloat16 g_hb[(size_t)Mdim*Cdim];          // bf16 GEMM input
__device__ __nv_bfloat16 g_qb[(size_t)Mdim*Cdim];
__device__ __nv_bfloat16 g_kb[(size_t)Mdim*Cdim];
__device__ __nv_bfloat16 g_vT[(size_t)Mdim*Cdim];          // [b][c][l]
__device__ __nv_bfloat16 g_ob[(size_t)Mdim*Cdim];          // attention out
__device__ __nv_bfloat16 g_sb[(size_t)Bdim*Ldim*Ldim];     // 67 MB P (unnormalized)
__device__ __nv_bfloat16 g_wq[Cdim*Cdim], g_wk[Cdim*Cdim]; // transposed bf16 weights
__device__ __nv_bfloat16 g_wv[Cdim*Cdim], g_wp[Cdim*Cdim];
__device__ float g_rowsum[Mdim];
__device__ float g_sum[64];
__device__ float g_ssum[64];

// ============================================================
// helpers
// ============================================================
__device__ __forceinline__ uint32_t smem_u32(const void* p) {
    uint32_t a;
    asm("{ .reg .u64 t; cvta.to.shared.u64 t, %1; cvt.u32.u64 %0, t; }"
        : "=r"(a) : "l"(p));
    return a;
}
__device__ __forceinline__ void cpa16(uint32_t dst, const void* src) {
    asm volatile("cp.async.cg.shared.global [%0], [%1], 16;"
                 :: "r"(dst), "l"(src) : "memory");
}
__device__ __forceinline__ void cpa_commit() {
    asm volatile("cp.async.commit_group;" ::: "memory");
}
template<int N> __device__ __forceinline__ void cpa_wait() {
    asm volatile("cp.async.wait_group %0;" :: "n"(N) : "memory");
}
__device__ __forceinline__ void mma16(float* d, const uint32_t* a, const uint32_t* b) {
    asm volatile(
        "mma.sync.aligned.m16n8k16.row.col.f32.bf16.bf16.f32 "
        "{%0,%1,%2,%3}, {%4,%5,%6,%7}, {%8,%9}, {%0,%1,%2,%3};"
        : "+f"(d[0]), "+f"(d[1]), "+f"(d[2]), "+f"(d[3])
        : "r"(a[0]), "r"(a[1]), "r"(a[2]), "r"(a[3]), "r"(b[0]), "r"(b[1]));
}
__device__ __forceinline__ void ldsm4(uint32_t* r, uint32_t addr) {
    asm volatile("ldmatrix.sync.aligned.m8n8.x4.shared.b16 {%0,%1,%2,%3}, [%4];"
        : "=r"(r[0]), "=r"(r[1]), "=r"(r[2]), "=r"(r[3]) : "r"(addr));
}

// ============================================================
// GroupNorm + zeros + weight convert/transpose
// ============================================================
__global__ void zeros_k() {
    int i = blockIdx.x * 256 + threadIdx.x;
    g_rowsum[i] = 0.f;
    if (i < 64) { g_sum[i] = 0.f; g_ssum[i] = 0.f; }
}

__global__ void gn_part(const float* __restrict__ x) {
    int chunk = blockIdx.x;            // 0..15
    int bg = blockIdx.y;               // 0..63
    int b = bg >> 3, g = bg & 7;
    const float* base = x + (size_t)b * Ldim * Cdim + (size_t)chunk * 128 * Cdim + g * 64;
    float s = 0.f, ss = 0.f;
#pragma unroll
    for (int i = 0; i < 8; i++) {
        int idx = threadIdx.x + i * 256;
        int row = idx >> 4, c4 = idx & 15;
        float4 v = *(const float4*)(base + (size_t)row * Cdim + c4 * 4);
        s += v.x + v.y + v.z + v.w;
        ss += v.x*v.x + v.y*v.y + v.z*v.z + v.w*v.w;
    }
#pragma unroll
    for (int o = 16; o > 0; o >>= 1) {
        s  += __shfl_xor_sync(0xffffffffu, s, o);
        ss += __shfl_xor_sync(0xffffffffu, ss, o);
    }
    __shared__ float sh1[8], sh2[8];
    int w = threadIdx.x >> 5;
    if ((threadIdx.x & 31) == 0) { sh1[w] = s; sh2[w] = ss; }
    __syncthreads();
    if (threadIdx.x == 0) {
        float t1 = 0.f, t2 = 0.f;
#pragma unroll
        for (int i = 0; i < 8; i++) { t1 += sh1[i]; t2 += sh2[i]; }
        atomicAdd(&g_sum[bg], t1);
        atomicAdd(&g_ssum[bg], t2);
    }
}

__global__ void gn_apply(const float4* __restrict__ x,
                         const float4* __restrict__ gamma,
                         const float4* __restrict__ beta) {
    int i = blockIdx.x * 256 + threadIdx.x;
    int e = i * 4;
    int ch = e & (Cdim - 1);
    int row = e >> 9;
    int b = row >> 11;
    int g = ch >> 6;
    const float inv = 1.f / (2048.f * 64.f);
    float m = g_sum[b * 8 + g] * inv;
    float r = rsqrtf(g_ssum[b * 8 + g] * inv - m * m + EPSV);
    float4 xv = x[i];
    float4 ga = gamma[ch >> 2];
    float4 be = beta[ch >> 2];
    float4 hv;
    hv.x = (xv.x - m) * r * ga.x + be.x;
    hv.y = (xv.y - m) * r * ga.y + be.y;
    hv.z = (xv.z - m) * r * ga.z + be.z;
    hv.w = (xv.w - m) * r * ga.w + be.w;
    ((float4*)g_h)[i] = hv;
    __nv_bfloat162 p0(__float2bfloat16(hv.x), __float2bfloat16(hv.y));
    __nv_bfloat162 p1(__float2bfloat16(hv.z), __float2bfloat16(hv.w));
    ((__nv_bfloat162*)g_hb)[i * 2]     = p0;
    ((__nv_bfloat162*)g_hb)[i * 2 + 1] = p1;
}

// fused transpose + bf16 convert of all 4 weights: wt[n][k] = w[k][n]
__global__ void wcvt4(const float* __restrict__ wq, const float* __restrict__ wk,
                      const float* __restrict__ wv, const float* __restrict__ wp) {
    const float* srcs[4] = {wq, wk, wv, wp};
    __nv_bfloat16* dsts[4] = {g_wq, g_wk, g_wv, g_wp};
    const float* w = srcs[blockIdx.z];
    __nv_bfloat16* wt = dsts[blockIdx.z];
    __shared__ float t[32][33];
    int bx = blockIdx.x * 32, by = blockIdx.y * 32;
    int tx = threadIdx.x, ty = threadIdx.y;   // 32 x 8
#pragma unroll
    for (int i = 0; i < 32; i += 8)
        t[ty + i][tx] = w[(size_t)(by + ty + i) * Cdim + bx + tx];
    __syncthreads();
#pragma unroll
    for (int i = 0; i < 32; i += 8)
        wt[(size_t)(bx + ty + i) * Cdim + by + tx] = __float2bfloat16(t[tx][ty + i]);
}

// ============================================================
// bf16 GEMM mainloop (3-stage cp.async, 1 barrier per BK=64 chunk)
// shared by gemm_bf<EPI> and gemm_qkv
// ============================================================
#define STAGE_B 36864
#define GEMM_SMEM (3*STAGE_B)     // 110592

struct MainLoop {
    uint32_t sb;
    const __nv_bfloat16 *Abase, *Bbase;
    int ldA, ldB, fr, fq;
    uint32_t aoff0, aoff1, boff;

    __device__ __forceinline__ void init(uint32_t sb_, const __nv_bfloat16* A,
                                         const __nv_bfloat16* B, int lA, int lB,
                                         int bm, int bn, int tid) {
        sb = sb_; ldA = lA; ldB = lB;
        fr = tid >> 3; fq = tid & 7;
        Abase = A + (size_t)bm * ldA;
        Bbase = B + (size_t)bn * ldB;
        int wid = tid >> 5, lid = tid & 31;
        int wm = wid & 3, wn = wid >> 2;
        aoff0 = (uint32_t)((wm * 32 + (lid & 15)) * 144 + (lid >> 4) * 16);
        aoff1 = aoff0 + 16 * 144;
        boff = (uint32_t)((wn * 64 + (lid & 7) + ((lid >> 4) & 1) * 8) * 144
                          + ((lid >> 3) & 1) * 16);
    }
    __device__ __forceinline__ void issue(int kc, int nch) {
        if (kc >= nch) return;
        int k0 = kc << 6;
        uint32_t as = sb + (kc % 3) * STAGE_B;
        uint32_t bs = as + 18432;
#pragma unroll
        for (int i = 0; i < 4; i++) {
            int r = fr + i * 32;
            cpa16(as + r * 144 + fq * 16, Abase + (size_t)r * ldA + k0 + fq * 8);
        }
#pragma unroll
        for (int i = 0; i < 4; i++) {
            int r = fr + i * 32;
            cpa16(bs + r * 144 + fq * 16, Bbase + (size_t)r * ldB + k0 + fq * 8);
        }
        cpa_commit();
    }
    __device__ __forceinline__ void run(float acc[2][8][4], int nch) {
        issue(0, nch);
        issue(1, nch);
        for (int kc = 0; kc < nch; kc++) {
            cpa_wait<1>();
            __syncthreads();
            issue(kc + 2, nch);
            uint32_t as = sb + (kc % 3) * STAGE_B;
            uint32_t bs = as + 18432;
#pragma unroll
            for (int s = 0; s < 4; s++) {
                uint32_t af[2][4];
                ldsm4(af[0], as + aoff0 + s * 32);
                ldsm4(af[1], as + aoff1 + s * 32);
                uint32_t bf[4][4];
#pragma unroll
                for (int np = 0; np < 4; np++)
                    ldsm4(bf[np], bs + boff + np * 16 * 144 + s * 32);
#pragma unroll
                for (int mt = 0; mt < 2; mt++)
#pragma unroll
                    for (int nt = 0; nt < 8; nt++)
                        mma16(acc[mt][nt], af[mt], &bf[nt >> 1][(nt & 1) * 2]);
            }
        }
    }
};

// ============================================================
// generic-epilogue GEMM (QKT / PV / out-proj)
//   EPI 2: exp(acc*SCALE) -> bf16, rowsum    (QKT)
//   EPI 3: acc/rowsum -> bf16 out            (PV)
//   EPI 4: +bias +res(fp32) -> fp32 out      (out-proj)
// ============================================================
template<int EPI>
__global__ void __launch_bounds__(256, 2)
gemm_bf(const __nv_bfloat16* __restrict__ A, const __nv_bfloat16* __restrict__ B,
        const float* __restrict__ bias, const float* __restrict__ res,
        float* __restrict__ rowsum, void* __restrict__ Cv,
        int Kn, int ldA, int ldB, int ldC, long sA, long sB, long sC) {
    extern __shared__ float smf[];
    int tid = threadIdx.x, wid = tid >> 5, lid = tid & 31;
    int wm = wid & 3, wn = wid >> 2;
    int z = blockIdx.z;
    int bm = blockIdx.y * 128, bn = blockIdx.x * 128;

    float acc[2][8][4];
#pragma unroll
    for (int mt = 0; mt < 2; mt++)
#pragma unroll
        for (int nt = 0; nt < 8; nt++)
#pragma unroll
            for (int i = 0; i < 4; i++) acc[mt][nt][i] = 0.f;

    MainLoop ml;
    ml.init(smem_u32(smf), A + (size_t)z * sA, B + (size_t)z * sB,
            ldA, ldB, bm, bn, tid);
    ml.run(acc, Kn >> 6);

    int c2 = (lid & 3) * 2;
    const int g = lid >> 2;
    float* rs = rowsum ? rowsum + z * Ldim : nullptr;
#pragma unroll
    for (int mt = 0; mt < 2; mt++) {
        int row0 = bm + wm * 32 + mt * 16 + g;
        if (EPI == 2) {
            __nv_bfloat16* C = (__nv_bfloat16*)Cv + (size_t)z * sC;
            float s0 = 0.f, s1 = 0.f;
#pragma unroll
            for (int nt = 0; nt < 8; nt++) {
                int col = bn + wn * 64 + nt * 8 + c2;
                float e00 = __expf(acc[mt][nt][0] * SCALE);
                float e01 = __expf(acc[mt][nt][1] * SCALE);
                float e10 = __expf(acc[mt][nt][2] * SCALE);
                float e11 = __expf(acc[mt][nt][3] * SCALE);
                s0 += e00 + e01; s1 += e10 + e11;
                *(__nv_bfloat162*)(C + (size_t)row0 * ldC + col) =
                    __nv_bfloat162(__float2bfloat16(e00), __float2bfloat16(e01));
                *(__nv_bfloat162*)(C + (size_t)(row0 + 8) * ldC + col) =
                    __nv_bfloat162(__float2bfloat16(e10), __float2bfloat16(e11));
            }
            s0 += __shfl_xor_sync(0xffffffffu, s0, 1);
            s0 += __shfl_xor_sync(0xffffffffu, s0, 2);
            s1 += __shfl_xor_sync(0xffffffffu, s1, 1);
            s1 += __shfl_xor_sync(0xffffffffu, s1, 2);
            if ((lid & 3) == 0) {
                atomicAdd(rs + row0, s0);
                atomicAdd(rs + row0 + 8, s1);
            }
        } else if (EPI == 3) {
            __nv_bfloat16* C = (__nv_bfloat16*)Cv + (size_t)z * sC;
            float inv0 = __fdividef(1.f, __ldg(rs + row0));
            float inv1 = __fdividef(1.f, __ldg(rs + row0 + 8));
#pragma unroll
            for (int nt = 0; nt < 8; nt++) {
                int col = bn + wn * 64 + nt * 8 + c2;
                *(__nv_bfloat162*)(C + (size_t)row0 * ldC + col) =
                    __nv_bfloat162(__float2bfloat16(acc[mt][nt][0] * inv0),
                                   __float2bfloat16(acc[mt][nt][1] * inv0));
                *(__nv_bfloat162*)(C + (size_t)(row0 + 8) * ldC + col) =
                    __nv_bfloat162(__float2bfloat16(acc[mt][nt][2] * inv1),
                                   __float2bfloat16(acc[mt][nt][3] * inv1));
            }
        } else {
            float* C = (float*)Cv;
#pragma unroll
            for (int nt = 0; nt < 8; nt++) {
                int col = bn + wn * 64 + nt * 8 + c2;
                float b0 = __ldg(bias + col), b1 = __ldg(bias + col + 1);
                const float* r0p = res + (size_t)row0 * ldC + col;
                const float* r1p = res + (size_t)(row0 + 8) * ldC + col;
                *(float2*)(C + (size_t)row0 * ldC + col) =
                    make_float2(acc[mt][nt][0] + b0 + r0p[0],
                                acc[mt][nt][1] + b1 + r0p[1]);
                *(float2*)(C + (size_t)(row0 + 8) * ldC + col) =
                    make_float2(acc[mt][nt][2] + b0 + r1p[0],
                                acc[mt][nt][3] + b1 + r1p[1]);
            }
        }
    }
}

// ============================================================
// fused QKV projection: grid.z selects {q, k, v}
//   z=0,1: bf16 out (qb/kb); z=2: bf16 transposed out (vT)
// ============================================================
__global__ void __launch_bounds__(256, 2)
gemm_qkv(const __nv_bfloat16* __restrict__ hb,
         const float* __restrict__ bq, const float* __restrict__ bk,
         const float* __restrict__ bv) {
    extern __shared__ float smf[];
    int tid = threadIdx.x, wid = tid >> 5, lid = tid & 31;
    int wm = wid & 3, wn = wid >> 2;
    int z = blockIdx.z;
    int bm = blockIdx.y * 128, bn = blockIdx.x * 128;

    const __nv_bfloat16* W = (z == 0) ? g_wq : (z == 1) ? g_wk : g_wv;
    const float* bias = (z == 0) ? bq : (z == 1) ? bk : bv;

    float acc[2][8][4];
#pragma unroll
    for (int mt = 0; mt < 2; mt++)
#pragma unroll
        for (int nt = 0; nt < 8; nt++)
#pragma unroll
            for (int i = 0; i < 4; i++) acc[mt][nt][i] = 0.f;

    MainLoop ml;
    ml.init(smem_u32(smf), hb, W, Cdim, Cdim, bm, bn, tid);
    ml.run(acc, Cdim >> 6);

    int c2 = (lid & 3) * 2;
    const int g = lid >> 2;
#pragma unroll
    for (int mt = 0; mt < 2; mt++) {
        int row0 = bm + wm * 32 + mt * 16 + g;
        if (z < 2) {
            __nv_bfloat16* C = (z == 0) ? g_qb : g_kb;
#pragma unroll
            for (int nt = 0; nt < 8; nt++) {
                int col = bn + wn * 64 + nt * 8 + c2;
                float b0 = __ldg(bias + col), b1 = __ldg(bias + col + 1);
                *(__nv_bfloat162*)(C + (size_t)row0 * Cdim + col) =
                    __nv_bfloat162(__float2bfloat16(acc[mt][nt][0] + b0),
                                   __float2bfloat16(acc[mt][nt][1] + b1));
                *(__nv_bfloat162*)(C + (size_t)(row0 + 8) * Cdim + col) =
                    __nv_bfloat162(__float2bfloat16(acc[mt][nt][2] + b0),
                                   __float2bfloat16(acc[mt][nt][3] + b1));
            }
        } else {
            int bz = row0 >> 11, l = row0 & 2047;
            __nv_bfloat16* VT = g_vT + (size_t)bz * Cdim * Ldim;
#pragma unroll
            for (int nt = 0; nt < 8; nt++) {
                int col = bn + wn * 64 + nt * 8 + c2;
                float b0 = __ldg(bias + col), b1 = __ldg(bias + col + 1);
                VT[(size_t)col * Ldim + l]           = __float2bfloat16(acc[mt][nt][0] + b0);
                VT[(size_t)(col + 1) * Ldim + l]     = __float2bfloat16(acc[mt][nt][1] + b1);
                VT[(size_t)col * Ldim + l + 8]       = __float2bfloat16(acc[mt][nt][2] + b0);
                VT[(size_t)(col + 1) * Ldim + l + 8] = __float2bfloat16(acc[mt][nt][3] + b1);
            }
        }
    }
}

// ============================================================
// Host launcher
// ============================================================
extern "C" void kernel_launch(void* const* d_in, const int* in_sizes, int n_in,
                              void* d_out, int out_size) {
    const float* x     = (const float*)d_in[0];
    const float* gamma = (const float*)d_in[1];
    const float* beta  = (const float*)d_in[2];
    const float* wq    = (const float*)d_in[3];
    const float* bq    = (const float*)d_in[4];
    const float* wk    = (const float*)d_in[5];
    const float* bk    = (const float*)d_in[6];
    const float* wv    = (const float*)d_in[7];
    const float* bv    = (const float*)d_in[8];
    const float* wp    = (const float*)d_in[9];
    const float* bp    = (const float*)d_in[10];
    float* out = (float*)d_out;

    float *h, *rs;
    __nv_bfloat16 *hb, *qb, *kb, *vT, *ob, *sbuf, *wpT;
    cudaGetSymbolAddress((void**)&h,  g_h);
    cudaGetSymbolAddress((void**)&hb, g_hb);
    cudaGetSymbolAddress((void**)&rs, g_rowsum);
    cudaGetSymbolAddress((void**)&qb, g_qb);
    cudaGetSymbolAddress((void**)&kb, g_kb);
    cudaGetSymbolAddress((void**)&vT, g_vT);
    cudaGetSymbolAddress((void**)&ob, g_ob);
    cudaGetSymbolAddress((void**)&sbuf, g_sb);
    cudaGetSymbolAddress((void**)&wpT, g_wp);

    static int smem_set = 0;
    if (!smem_set) {
        cudaFuncSetAttribute(gemm_qkv,   cudaFuncAttributeMaxDynamicSharedMemorySize, GEMM_SMEM);
        cudaFuncSetAttribute(gemm_bf<2>, cudaFuncAttributeMaxDynamicSharedMemorySize, GEMM_SMEM);
        cudaFuncSetAttribute(gemm_bf<3>, cudaFuncAttributeMaxDynamicSharedMemorySize, GEMM_SMEM);
        cudaFuncSetAttribute(gemm_bf<4>, cudaFuncAttributeMaxDynamicSharedMemorySize, GEMM_SMEM);
        smem_set = 1;
    }

    const long LC = (long)Ldim * Cdim;
    const long LL = (long)Ldim * Ldim;

    // 1) GroupNorm + zeros + weight transposes
    zeros_k<<<64, 256>>>();
    gn_part<<<dim3(16, 64), 256>>>(x);
    gn_apply<<<(Mdim * Cdim / 4) / 256, 256>>>(
        (const float4*)x, (const float4*)gamma, (const float4*)beta);
    wcvt4<<<dim3(16, 16, 4), dim3(32, 8)>>>(wq, wk, wv, wp);

    // 2) fused Q/K/V projections
    gemm_qkv<<<dim3(Cdim / 128, Mdim / 128, 3), 256, GEMM_SMEM>>>(hb, bq, bk, bv);

    // 3) P_unnorm = exp(scale * Q K^T), rowsum partials
    dim3 gS(Ldim / 128, Ldim / 128, Bdim);
    gemm_bf<2><<<gS, 256, GEMM_SMEM>>>(qb, kb, nullptr, nullptr, rs, sbuf,
                                       Cdim, Cdim, Cdim, Ldim, LC, LC, LL);

    // 4) O = (P_unnorm @ V) / rowsum  -> bf16
    dim3 gPV(Cdim / 128, Ldim / 128, Bdim);
    gemm_bf<3><<<gPV, 256, GEMM_SMEM>>>(sbuf, vT, nullptr, nullptr, rs, ob,
                                        Ldim, Ldim, Ldim, Cdim, LL, LC, LC);

    // 5) out = h + (O @ wp + bp)
    dim3 gProj(Cdim / 128, Mdim / 128, 1);
    gemm_bf<4><<<gProj, 256, GEMM_SMEM>>>(ob, wpT, bp, h, nullptr, out,
                                          Cdim, Cdim, Cdim, Cdim, 0, 0, 0);
}

// round 16
// speedup vs baseline: 7.3972x; 1.0019x over previous
#include <cuda_runtime.h>
#include <cuda_bf16.h>
#include <math.h>
#include <stdint.h>

#define Bdim 8
#define Ldim 2048
#define Cdim 512
#define Mdim (Bdim*Ldim)          // 16384
#define EPSV 1e-3f
#define SCALE 0.04419417382415922f  // 512^-0.5

// ---- scratch (device globals: allocation-free rule) ----
__device__ float g_h[(size_t)Mdim*Cdim];                   // fp32 residual
__device__ __nv_bfloat16 g_hb[(size_t)Mdim*Cdim];          // bf16 GEMM input
__device__ __nv_bfloat16 g_qb[(size_t)Mdim*Cdim];
__device__ __nv_bfloat16 g_kb[(size_t)Mdim*Cdim];
__device__ __nv_bfloat16 g_vT[(size_t)Mdim*Cdim];          // [b][c][l]
__device__ __nv_bfloat16 g_ob[(size_t)Mdim*Cdim];          // attention out
__device__ __nv_bfloat16 g_sb[(size_t)Bdim*Ldim*Ldim];     // 67 MB P (unnormalized)
__device__ __nv_bfloat16 g_wq[Cdim*Cdim], g_wk[Cdim*Cdim]; // transposed bf16 weights
__device__ __nv_bfloat16 g_wv[Cdim*Cdim], g_wp[Cdim*Cdim];
__device__ float g_rowsum[Mdim];
__device__ float g_sum[64];
__device__ float g_ssum[64];

// ============================================================
// helpers
// ============================================================
__device__ __forceinline__ uint32_t smem_u32(const void* p) {
    uint32_t a;
    asm("{ .reg .u64 t; cvta.to.shared.u64 t, %1; cvt.u32.u64 %0, t; }"
        : "=r"(a) : "l"(p));
    return a;
}
__device__ __forceinline__ void cpa16(uint32_t dst, const void* src) {
    asm volatile("cp.async.cg.shared.global [%0], [%1], 16;"
                 :: "r"(dst), "l"(src) : "memory");
}
__device__ __forceinline__ void cpa_commit() {
    asm volatile("cp.async.commit_group;" ::: "memory");
}
template<int N> __device__ __forceinline__ void cpa_wait() {
    asm volatile("cp.async.wait_group %0;" :: "n"(N) : "memory");
}
__device__ __forceinline__ void mma16(float* d, const uint32_t* a, const uint32_t* b) {
    asm volatile(
        "mma.sync.aligned.m16n8k16.row.col.f32.bf16.bf16.f32 "
        "{%0,%1,%2,%3}, {%4,%5,%6,%7}, {%8,%9}, {%0,%1,%2,%3};"
        : "+f"(d[0]), "+f"(d[1]), "+f"(d[2]), "+f"(d[3])
        : "r"(a[0]), "r"(a[1]), "r"(a[2]), "r"(a[3]), "r"(b[0]), "r"(b[1]));
}
__device__ __forceinline__ void ldsm4(uint32_t* r, uint32_t addr) {
    asm volatile("ldmatrix.sync.aligned.m8n8.x4.shared.b16 {%0,%1,%2,%3}, [%4];"
        : "=r"(r[0]), "=r"(r[1]), "=r"(r[2]), "=r"(r[3]) : "r"(addr));
}

// ============================================================
// GroupNorm + zeros + weight convert/transpose
// ============================================================
__global__ void zeros_k() {
    int i = blockIdx.x * 256 + threadIdx.x;
    g_rowsum[i] = 0.f;
    if (i < 64) { g_sum[i] = 0.f; g_ssum[i] = 0.f; }
}

__global__ void gn_part(const float* __restrict__ x) {
    int chunk = blockIdx.x;            // 0..15
    int bg = blockIdx.y;               // 0..63
    int b = bg >> 3, g = bg & 7;
    const float* base = x + (size_t)b * Ldim * Cdim + (size_t)chunk * 128 * Cdim + g * 64;
    float s = 0.f, ss = 0.f;
#pragma unroll
    for (int i = 0; i < 8; i++) {
        int idx = threadIdx.x + i * 256;
        int row = idx >> 4, c4 = idx & 15;
        float4 v = *(const float4*)(base + (size_t)row * Cdim + c4 * 4);
        s += v.x + v.y + v.z + v.w;
        ss += v.x*v.x + v.y*v.y + v.z*v.z + v.w*v.w;
    }
#pragma unroll
    for (int o = 16; o > 0; o >>= 1) {
        s  += __shfl_xor_sync(0xffffffffu, s, o);
        ss += __shfl_xor_sync(0xffffffffu, ss, o);
    }
    __shared__ float sh1[8], sh2[8];
    int w = threadIdx.x >> 5;
    if ((threadIdx.x & 31) == 0) { sh1[w] = s; sh2[w] = ss; }
    __syncthreads();
    if (threadIdx.x == 0) {
        float t1 = 0.f, t2 = 0.f;
#pragma unroll
        for (int i = 0; i < 8; i++) { t1 += sh1[i]; t2 += sh2[i]; }
        atomicAdd(&g_sum[bg], t1);
        atomicAdd(&g_ssum[bg], t2);
    }
}

__global__ void gn_apply(const float4* __restrict__ x,
                         const float4* __restrict__ gamma,
                         const float4* __restrict__ beta) {
    int i = blockIdx.x * 256 + threadIdx.x;
    int e = i * 4;
    int ch = e & (Cdim - 1);
    int row = e >> 9;
    int b = row >> 11;
    int g = ch >> 6;
    const float inv = 1.f / (2048.f * 64.f);
    float m = g_sum[b * 8 + g] * inv;
    float r = rsqrtf(g_ssum[b * 8 + g] * inv - m * m + EPSV);
    float4 xv = x[i];
    float4 ga = gamma[ch >> 2];
    float4 be = beta[ch >> 2];
    float4 hv;
    hv.x = (xv.x - m) * r * ga.x + be.x;
    hv.y = (xv.y - m) * r * ga.y + be.y;
    hv.z = (xv.z - m) * r * ga.z + be.z;
    hv.w = (xv.w - m) * r * ga.w + be.w;
    ((float4*)g_h)[i] = hv;
    __nv_bfloat162 p0(__float2bfloat16(hv.x), __float2bfloat16(hv.y));
    __nv_bfloat162 p1(__float2bfloat16(hv.z), __float2bfloat16(hv.w));
    ((__nv_bfloat162*)g_hb)[i * 2]     = p0;
    ((__nv_bfloat162*)g_hb)[i * 2 + 1] = p1;
}

// fused transpose + bf16 convert of all 4 weights: wt[n][k] = w[k][n]
__global__ void wcvt4(const float* __restrict__ wq, const float* __restrict__ wk,
                      const float* __restrict__ wv, const float* __restrict__ wp) {
    const float* srcs[4] = {wq, wk, wv, wp};
    __nv_bfloat16* dsts[4] = {g_wq, g_wk, g_wv, g_wp};
    const float* w = srcs[blockIdx.z];
    __nv_bfloat16* wt = dsts[blockIdx.z];
    __shared__ float t[32][33];
    int bx = blockIdx.x * 32, by = blockIdx.y * 32;
    int tx = threadIdx.x, ty = threadIdx.y;   // 32 x 8
#pragma unroll
    for (int i = 0; i < 32; i += 8)
        t[ty + i][tx] = w[(size_t)(by + ty + i) * Cdim + bx + tx];
    __syncthreads();
#pragma unroll
    for (int i = 0; i < 32; i += 8)
        wt[(size_t)(bx + ty + i) * Cdim + by + tx] = __float2bfloat16(t[tx][ty + i]);
}

// ============================================================
// bf16 GEMM mainloop (3-stage cp.async)
// SAFE ordering: cpa_wait -> __syncthreads -> issue(kc+2) -> compute.
// The barrier AFTER the wait is what publishes all threads' cp.async
// completions before any thread's ldmatrix reads — do not reorder.
// ============================================================
#define STAGE_B 36864
#define GEMM_SMEM (3*STAGE_B)     // 110592

struct MainLoop {
    uint32_t sb;
    const __nv_bfloat16 *Abase, *Bbase;
    int ldA, ldB, fr, fq;
    uint32_t aoff0, aoff1, boff;

    __device__ __forceinline__ void init(uint32_t sb_, const __nv_bfloat16* A,
                                         const __nv_bfloat16* B, int lA, int lB,
                                         int bm, int bn, int tid) {
        sb = sb_; ldA = lA; ldB = lB;
        fr = tid >> 3; fq = tid & 7;
        Abase = A + (size_t)bm * ldA;
        Bbase = B + (size_t)bn * ldB;
        int wid = tid >> 5, lid = tid & 31;
        int wm = wid & 3, wn = wid >> 2;
        aoff0 = (uint32_t)((wm * 32 + (lid & 15)) * 144 + (lid >> 4) * 16);
        aoff1 = aoff0 + 16 * 144;
        boff = (uint32_t)((wn * 64 + (lid & 7) + ((lid >> 4) & 1) * 8) * 144
                          + ((lid >> 3) & 1) * 16);
    }
    __device__ __forceinline__ void issue(int kc, uint32_t as) {
        int k0 = kc << 6;
        uint32_t bs = as + 18432;
#pragma unroll
        for (int i = 0; i < 4; i++) {
            int r = fr + i * 32;
            cpa16(as + r * 144 + fq * 16, Abase + (size_t)r * ldA + k0 + fq * 8);
        }
#pragma unroll
        for (int i = 0; i < 4; i++) {
            int r = fr + i * 32;
            cpa16(bs + r * 144 + fq * 16, Bbase + (size_t)r * ldB + k0 + fq * 8);
        }
        cpa_commit();
    }
    __device__ __forceinline__ void run(float acc[2][8][4], int nch) {
        issue(0, sb);
        if (nch > 1) issue(1, sb + STAGE_B);
        uint32_t st_w = sb + 2 * STAGE_B;       // next write stage
        uint32_t st_r = sb;                     // next read stage
        for (int kc = 0; kc < nch; kc++) {
            if (kc + 1 < nch) cpa_wait<1>();
            else cpa_wait<0>();
            __syncthreads();                    // publish ALL threads' cp.async data
            if (kc + 2 < nch) {
                issue(kc + 2, st_w);
                st_w += STAGE_B; if (st_w == sb + 3 * STAGE_B) st_w = sb;
            }
            uint32_t as = st_r;
            uint32_t bs = as + 18432;
            st_r += STAGE_B; if (st_r == sb + 3 * STAGE_B) st_r = sb;
#pragma unroll
            for (int s = 0; s < 4; s++) {
                uint32_t af[2][4];
                ldsm4(af[0], as + aoff0 + s * 32);
                ldsm4(af[1], as + aoff1 + s * 32);
                uint32_t bf[4][4];
#pragma unroll
                for (int np = 0; np < 4; np++)
                    ldsm4(bf[np], bs + boff + np * 16 * 144 + s * 32);
#pragma unroll
                for (int mt = 0; mt < 2; mt++)
#pragma unroll
                    for (int nt = 0; nt < 8; nt++)
                        mma16(acc[mt][nt], af[mt], &bf[nt >> 1][(nt & 1) * 2]);
            }
        }
    }
};

// ============================================================
// generic-epilogue GEMM (QKT / PV / out-proj)
//   EPI 2: exp(acc*SCALE) -> bf16, rowsum    (QKT)
//   EPI 3: acc/rowsum -> bf16 out            (PV)
//   EPI 4: +bias +res(fp32) -> fp32 out      (out-proj)
// ============================================================
template<int EPI>
__global__ void __launch_bounds__(256, 2)
gemm_bf(const __nv_bfloat16* __restrict__ A, const __nv_bfloat16* __restrict__ B,
        const float* __restrict__ bias, const float* __restrict__ res,
        float* __restrict__ rowsum, void* __restrict__ Cv,
        int Kn, int ldA, int ldB, int ldC, long sA, long sB, long sC) {
    extern __shared__ float smf[];
    int tid = threadIdx.x, wid = tid >> 5, lid = tid & 31;
    int wm = wid & 3, wn = wid >> 2;
    int z = blockIdx.z;
    int bm = blockIdx.y * 128, bn = blockIdx.x * 128;

    float acc[2][8][4];
#pragma unroll
    for (int mt = 0; mt < 2; mt++)
#pragma unroll
        for (int nt = 0; nt < 8; nt++)
#pragma unroll
            for (int i = 0; i < 4; i++) acc[mt][nt][i] = 0.f;

    MainLoop ml;
    ml.init(smem_u32(smf), A + (size_t)z * sA, B + (size_t)z * sB,
            ldA, ldB, bm, bn, tid);
    ml.run(acc, Kn >> 6);

    int c2 = (lid & 3) * 2;
    const int g = lid >> 2;
    float* rs = rowsum ? rowsum + z * Ldim : nullptr;
#pragma unroll
    for (int mt = 0; mt < 2; mt++) {
        int row0 = bm + wm * 32 + mt * 16 + g;
        if (EPI == 2) {
            __nv_bfloat16* C = (__nv_bfloat16*)Cv + (size_t)z * sC;
            float s0 = 0.f, s1 = 0.f;
#pragma unroll
            for (int nt = 0; nt < 8; nt++) {
                int col = bn + wn * 64 + nt * 8 + c2;
                float e00 = __expf(acc[mt][nt][0] * SCALE);
                float e01 = __expf(acc[mt][nt][1] * SCALE);
                float e10 = __expf(acc[mt][nt][2] * SCALE);
                float e11 = __expf(acc[mt][nt][3] * SCALE);
                s0 += e00 + e01; s1 += e10 + e11;
                *(__nv_bfloat162*)(C + (size_t)row0 * ldC + col) =
                    __nv_bfloat162(__float2bfloat16(e00), __float2bfloat16(e01));
                *(__nv_bfloat162*)(C + (size_t)(row0 + 8) * ldC + col) =
                    __nv_bfloat162(__float2bfloat16(e10), __float2bfloat16(e11));
            }
            s0 += __shfl_xor_sync(0xffffffffu, s0, 1);
            s0 += __shfl_xor_sync(0xffffffffu, s0, 2);
            s1 += __shfl_xor_sync(0xffffffffu, s1, 1);
            s1 += __shfl_xor_sync(0xffffffffu, s1, 2);
            if ((lid & 3) == 0) {
                atomicAdd(rs + row0, s0);
                atomicAdd(rs + row0 + 8, s1);
            }
        } else if (EPI == 3) {
            __nv_bfloat16* C = (__nv_bfloat16*)Cv + (size_t)z * sC;
            float inv0 = __fdividef(1.f, __ldg(rs + row0));
            float inv1 = __fdividef(1.f, __ldg(rs + row0 + 8));
#pragma unroll
            for (int nt = 0; nt < 8; nt++) {
                int col = bn + wn * 64 + nt * 8 + c2;
                *(__nv_bfloat162*)(C + (size_t)row0 * ldC + col) =
                    __nv_bfloat162(__float2bfloat16(acc[mt][nt][0] * inv0),
                                   __float2bfloat16(acc[mt][nt][1] * inv0));
                *(__nv_bfloat162*)(C + (size_t)(row0 + 8) * ldC + col) =
                    __nv_bfloat162(__float2bfloat16(acc[mt][nt][2] * inv1),
                                   __float2bfloat16(acc[mt][nt][3] * inv1));
            }
        } else {
            float* C = (float*)Cv;
#pragma unroll
            for (int nt = 0; nt < 8; nt++) {
                int col = bn + wn * 64 + nt * 8 + c2;
                float b0 = __ldg(bias + col), b1 = __ldg(bias + col + 1);
                const float* r0p = res + (size_t)row0 * ldC + col;
                const float* r1p = res + (size_t)(row0 + 8) * ldC + col;
                *(float2*)(C + (size_t)row0 * ldC + col) =
                    make_float2(acc[mt][nt][0] + b0 + r0p[0],
                                acc[mt][nt][1] + b1 + r0p[1]);
                *(float2*)(C + (size_t)(row0 + 8) * ldC + col) =
                    make_float2(acc[mt][nt][2] + b0 + r1p[0],
                                acc[mt][nt][3] + b1 + r1p[1]);
            }
        }
    }
}

// ============================================================
// fused QKV projection: grid.z selects {q, k, v}
// ============================================================
__global__ void __launch_bounds__(256, 2)
gemm_qkv(const __nv_bfloat16* __restrict__ hb,
         const float* __restrict__ bq, const float* __restrict__ bk,
         const float* __restrict__ bv) {
    extern __shared__ float smf[];
    int tid = threadIdx.x, wid = tid >> 5, lid = tid & 31;
    int wm = wid & 3, wn = wid >> 2;
    int z = blockIdx.z;
    int bm = blockIdx.y * 128, bn = blockIdx.x * 128;

    const __nv_bfloat16* W = (z == 0) ? g_wq : (z == 1) ? g_wk : g_wv;
    const float* bias = (z == 0) ? bq : (z == 1) ? bk : bv;

    float acc[2][8][4];
#pragma unroll
    for (int mt = 0; mt < 2; mt++)
#pragma unroll
        for (int nt = 0; nt < 8; nt++)
#pragma unroll
            for (int i = 0; i < 4; i++) acc[mt][nt][i] = 0.f;

    MainLoop ml;
    ml.init(smem_u32(smf), hb, W, Cdim, Cdim, bm, bn, tid);
    ml.run(acc, Cdim >> 6);

    int c2 = (lid & 3) * 2;
    const int g = lid >> 2;
#pragma unroll
    for (int mt = 0; mt < 2; mt++) {
        int row0 = bm + wm * 32 + mt * 16 + g;
        if (z < 2) {
            __nv_bfloat16* C = (z == 0) ? g_qb : g_kb;
#pragma unroll
            for (int nt = 0; nt < 8; nt++) {
                int col = bn + wn * 64 + nt * 8 + c2;
                float b0 = __ldg(bias + col), b1 = __ldg(bias + col + 1);
                *(__nv_bfloat162*)(C + (size_t)row0 * Cdim + col) =
                    __nv_bfloat162(__float2bfloat16(acc[mt][nt][0] + b0),
                                   __float2bfloat16(acc[mt][nt][1] + b1));
                *(__nv_bfloat162*)(C + (size_t)(row0 + 8) * Cdim + col) =
                    __nv_bfloat162(__float2bfloat16(acc[mt][nt][2] + b0),
                                   __float2bfloat16(acc[mt][nt][3] + b1));
            }
        } else {
            int bz = row0 >> 11, l = row0 & 2047;
            __nv_bfloat16* VT = g_vT + (size_t)bz * Cdim * Ldim;
#pragma unroll
            for (int nt = 0; nt < 8; nt++) {
                int col = bn + wn * 64 + nt * 8 + c2;
                float b0 = __ldg(bias + col), b1 = __ldg(bias + col + 1);
                VT[(size_t)col * Ldim + l]           = __float2bfloat16(acc[mt][nt][0] + b0);
                VT[(size_t)(col + 1) * Ldim + l]     = __float2bfloat16(acc[mt][nt][1] + b1);
                VT[(size_t)col * Ldim + l + 8]       = __float2bfloat16(acc[mt][nt][2] + b0);
                VT[(size_t)(col + 1) * Ldim + l + 8] = __float2bfloat16(acc[mt][nt][3] + b1);
            }
        }
    }
}

// ============================================================
// Host launcher (fork-join: wcvt4 overlaps gn chain)
// ============================================================
extern "C" void kernel_launch(void* const* d_in, const int* in_sizes, int n_in,
                              void* d_out, int out_size) {
    const float* x     = (const float*)d_in[0];
    const float* gamma = (const float*)d_in[1];
    const float* beta  = (const float*)d_in[2];
    const float* wq    = (const float*)d_in[3];
    const float* bq    = (const float*)d_in[4];
    const float* wk    = (const float*)d_in[5];
    const float* bk    = (const float*)d_in[6];
    const float* wv    = (const float*)d_in[7];
    const float* bv    = (const float*)d_in[8];
    const float* wp    = (const float*)d_in[9];
    const float* bp    = (const float*)d_in[10];
    float* out = (float*)d_out;

    float *h, *rs;
    __nv_bfloat16 *hb, *qb, *kb, *vT, *ob, *sbuf, *wpT;
    cudaGetSymbolAddress((void**)&h,  g_h);
    cudaGetSymbolAddress((void**)&hb, g_hb);
    cudaGetSymbolAddress((void**)&rs, g_rowsum);
    cudaGetSymbolAddress((void**)&qb, g_qb);
    cudaGetSymbolAddress((void**)&kb, g_kb);
    cudaGetSymbolAddress((void**)&vT, g_vT);
    cudaGetSymbolAddress((void**)&ob, g_ob);
    cudaGetSymbolAddress((void**)&sbuf, g_sb);
    cudaGetSymbolAddress((void**)&wpT, g_wp);

    static cudaStream_t s_side = nullptr;
    static cudaEvent_t ev_fork = nullptr, ev_join = nullptr;
    static int smem_set = 0;
    if (!smem_set) {
        cudaFuncSetAttribute(gemm_qkv,   cudaFuncAttributeMaxDynamicSharedMemorySize, GEMM_SMEM);
        cudaFuncSetAttribute(gemm_bf<2>, cudaFuncAttributeMaxDynamicSharedMemorySize, GEMM_SMEM);
        cudaFuncSetAttribute(gemm_bf<3>, cudaFuncAttributeMaxDynamicSharedMemorySize, GEMM_SMEM);
        cudaFuncSetAttribute(gemm_bf<4>, cudaFuncAttributeMaxDynamicSharedMemorySize, GEMM_SMEM);
        cudaStreamCreateWithFlags(&s_side, cudaStreamNonBlocking);
        cudaEventCreateWithFlags(&ev_fork, cudaEventDisableTiming);
        cudaEventCreateWithFlags(&ev_join, cudaEventDisableTiming);
        smem_set = 1;
    }

    const long LC = (long)Ldim * Cdim;
    const long LL = (long)Ldim * Ldim;

    // 1) zeros, then fork: gn chain (main) || weight transpose (side)
    zeros_k<<<64, 256>>>();
    cudaEventRecord(ev_fork, 0);
    cudaStreamWaitEvent(s_side, ev_fork, 0);
    wcvt4<<<dim3(16, 16, 4), dim3(32, 8), 0, s_side>>>(wq, wk, wv, wp);
    cudaEventRecord(ev_join, s_side);
    gn_part<<<dim3(16, 64), 256>>>(x);
    gn_apply<<<(Mdim * Cdim / 4) / 256, 256>>>(
        (const float4*)x, (const float4*)gamma, (const float4*)beta);
    cudaStreamWaitEvent(0, ev_join, 0);

    // 2) fused Q/K/V projections
    gemm_qkv<<<dim3(Cdim / 128, Mdim / 128, 3), 256, GEMM_SMEM>>>(hb, bq, bk, bv);

    // 3) P_unnorm = exp(scale * Q K^T), rowsum partials
    dim3 gS(Ldim / 128, Ldim / 128, Bdim);
    gemm_bf<2><<<gS, 256, GEMM_SMEM>>>(qb, kb, nullptr, nullptr, rs, sbuf,
                                       Cdim, Cdim, Cdim, Ldim, LC, LC, LL);

    // 4) O = (P_unnorm @ V) / rowsum  -> bf16
    dim3 gPV(Cdim / 128, Ldim / 128, Bdim);
    gemm_bf<3><<<gPV, 256, GEMM_SMEM>>>(sbuf, vT, nullptr, nullptr, rs, ob,
                                        Ldim, Ldim, Ldim, Cdim, LL, LC, LC);

    // 5) out = h + (O @ wp + bp)
    dim3 gProj(Cdim / 128, Mdim / 128, 1);
    gemm_bf<4><<<gProj, 256, GEMM_SMEM>>>(ob, wpT, bp, h, nullptr, out,
                                          Cdim, Cdim, Cdim, Cdim, 0, 0, 0);
}